// round 6
// baseline (speedup 1.0000x reference)
#include <cuda_runtime.h>
#include <cuda_bf16.h>
#include <math.h>
#include <stdint.h>

#define NN     20000
#define TT     32
#define INP    64
#define HH     128
#define G3     384
#define SS     64
#define EINTRA 640000
#define EINTER 4096

// ---------------- scratch (static device globals; no allocs) ----------------
__device__ __align__(128) float g_gi[(size_t)NN*TT*G3];            // 983 MB (gate-interleaved cols)
__device__ __align__(128) __nv_bfloat16 g_xb[(size_t)NN*TT*2*INP]; // x as hi|lo
__device__ __align__(128) __nv_bfloat16 g_o0b[(size_t)NN*TT*2*HH]; // layer0 outputs hi|lo
__device__ __align__(128) float g_h[(size_t)NN*HH];
__device__ __align__(128) __nv_bfloat16 g_hbA[(size_t)NN*2*HH];
__device__ __align__(128) __nv_bfloat16 g_hbB[(size_t)NN*2*HH];
__device__ __align__(128) float g_hlin[(size_t)NN*HH];
__device__ __align__(128) float g_acc[(size_t)NN*HH];
__device__ __align__(128) __nv_bfloat16 g_wb_ih0[G3*2*INP];   // gate-interleaved rows
__device__ __align__(128) __nv_bfloat16 g_wb_hh0[G3*2*HH];    // gate-interleaved rows
__device__ __align__(128) __nv_bfloat16 g_wb_ih1[G3*2*HH];    // gate-interleaved rows
__device__ __align__(128) __nv_bfloat16 g_wb_hh1[G3*2*HH];    // gate-interleaved rows
__device__ __align__(128) __nv_bfloat16 g_wb_intra[HH*2*HH];
__device__ __align__(128) __nv_bfloat16 g_wb_inter[HH*2*HH];
__device__ float    g_es[NN];
__device__ float    g_ed[NN];
__device__ float    g_m[NN];
__device__ float    g_den[NN];
__device__ unsigned g_mu[NN];
__device__ float    g_eedge[EINTRA];
__device__ unsigned g_pu[SS*HH];
__device__ __align__(128) float g_pool[SS*HH];
__device__ __align__(128) __nv_bfloat16 g_poolb[SS*2*HH];
__device__ __align__(128) float g_shlin[SS*HH];
__device__ __align__(128) float g_sacc[SS*HH];

// ---------------- helpers ----------------
__device__ __forceinline__ uint32_t smem_u32(const void* p) {
    uint32_t a;
    asm("{ .reg .u64 t; cvta.to.shared.u64 t, %1; cvt.u32.u64 %0, t; }" : "=r"(a) : "l"(p));
    return a;
}
__device__ __forceinline__ unsigned fkey(float f) {
    unsigned u = __float_as_uint(f);
    return (u & 0x80000000u) ? ~u : (u | 0x80000000u);
}
__device__ __forceinline__ float funkey(unsigned k) {
    return (k & 0x80000000u) ? __uint_as_float(k & 0x7fffffffu)
                             : __uint_as_float(~k);
}
__device__ __forceinline__ float lrelu(float x) { return x > 0.f ? x : 0.2f * x; }

__device__ __forceinline__ void cp_async16(uint32_t saddr, const void* gaddr, int srcBytes) {
    asm volatile("cp.async.cg.shared.global [%0], [%1], 16, %2;"
                 :: "r"(saddr), "l"(gaddr), "r"(srcBytes) : "memory");
}
__device__ __forceinline__ void cp_commit() {
    asm volatile("cp.async.commit_group;" ::: "memory");
}
template <int N>
__device__ __forceinline__ void cp_wait() {
    asm volatile("cp.async.wait_group %0;" :: "n"(N) : "memory");
}
__device__ __forceinline__ void ldmatrix_x4(uint32_t* r, uint32_t addr) {
    asm volatile("ldmatrix.sync.aligned.m8n8.x4.shared.b16 {%0,%1,%2,%3}, [%4];"
                 : "=r"(r[0]), "=r"(r[1]), "=r"(r[2]), "=r"(r[3]) : "r"(addr));
}
__device__ __forceinline__ void mma16816(float* d, const uint32_t* a, uint32_t b0, uint32_t b1) {
    asm volatile(
        "mma.sync.aligned.m16n8k16.row.col.f32.bf16.bf16.f32 "
        "{%0,%1,%2,%3}, {%4,%5,%6,%7}, {%8,%9}, {%0,%1,%2,%3};"
        : "+f"(d[0]), "+f"(d[1]), "+f"(d[2]), "+f"(d[3])
        : "r"(a[0]), "r"(a[1]), "r"(a[2]), "r"(a[3]), "r"(b0), "r"(b1));
}

// ---------------- misc kernels ----------------
__global__ void zerof_k(float* p, int n) {
    int i = blockIdx.x * blockDim.x + threadIdx.x;
    if (i < n) p[i] = 0.f;
}
__global__ void zerou_k(unsigned* p, int n) {
    int i = blockIdx.x * blockDim.x + threadIdx.x;
    if (i < n) p[i] = 0u;
}
// split fp32 [rows,K] -> bf16 [rows, 2K] as [hi | lo]
__global__ void convw_k(const float* __restrict__ W, __nv_bfloat16* __restrict__ Wb,
                        int rows, int K) {
    int idx = blockIdx.x * blockDim.x + threadIdx.x;
    if (idx >= rows * K) return;
    int r = idx / K, c = idx % K;
    float v = W[idx];
    __nv_bfloat16 hi = __float2bfloat16(v);
    __nv_bfloat16 lo = __float2bfloat16(v - __bfloat162float(hi));
    Wb[(size_t)r * 2 * K + c]     = hi;
    Wb[(size_t)r * 2 * K + K + c] = lo;
}
// GRU weight conv with gate interleave: out row 3u+g <- in row g*128+u. W [384,K].
__global__ void convw_int_k(const float* __restrict__ W, __nv_bfloat16* __restrict__ Wb, int K) {
    int idx = blockIdx.x * blockDim.x + threadIdx.x;
    if (idx >= G3 * K) return;
    int rr = idx / K, c = idx % K;
    int u = rr / 3, g = rr % 3;
    float v = W[(size_t)(g * HH + u) * K + c];
    __nv_bfloat16 hi = __float2bfloat16(v);
    __nv_bfloat16 lo = __float2bfloat16(v - __bfloat162float(hi));
    Wb[(size_t)rr * 2 * K + c]     = hi;
    Wb[(size_t)rr * 2 * K + K + c] = lo;
}

// ---------------- tensor-core GEMM (mma.sync bf16): C = split(A) @ split(B)^T ----
// Ab [M, 2K] bf16 (hi|lo), Bb [Nc, 2K] bf16 (hi|lo), C [M,Nc] fp32.
// Computes Ahi@Bhi^T + Alo@Bhi^T + Ahi@Blo^T. Tile 128x128xBK32, cp.async
// double buffer, XOR-swizzled smem, 8 warps each 32x64.
// grid = (Nc/128, ceil(M/128)); Nc % 128 == 0; K % 32 == 0.
__global__ void __launch_bounds__(256) gemm_mma_k(
    const __nv_bfloat16* __restrict__ Ab,
    const __nv_bfloat16* __restrict__ Bb,
    float* __restrict__ C, int M, int Nc, int K)
{
    __shared__ __align__(16) char smbuf[32768];  // [2 stages][A 8K | B 8K]
    const uint32_t sb = smem_u32(smbuf);
    const int tid = threadIdx.x;
    const int wid = tid >> 5, lane = tid & 31;
    const int wm = wid & 3;          // warp row  (32 rows)
    const int wn = wid >> 2;         // warp col  (64 cols)
    const int bm = blockIdx.y * 128;
    const int bn = blockIdx.x * 128;
    const int ldab = 2 * K;          // bf16 elems per row of Ab/Bb

    const int cpk = K >> 5;          // 32-elem chunks per K segment
    const int nk = 3 * cpk;

    float d[2][8][4];
#pragma unroll
    for (int i = 0; i < 2; i++)
#pragma unroll
        for (int j = 0; j < 8; j++)
#pragma unroll
            for (int q = 0; q < 4; q++) d[i][j][q] = 0.f;

    auto issue_loads = [&](int kb, int s) {
        const int seg = kb / cpk, kc = kb - seg * cpk;
        const int acol = (seg == 1 ? K : 0) + (kc << 5);
        const int bcol = (seg == 2 ? K : 0) + (kc << 5);
        const __nv_bfloat16* Abase = Ab + acol;
        const __nv_bfloat16* Bbase = Bb + bcol;
        const uint32_t sA = sb + s * 16384;
        const uint32_t sB = sA + 8192;
#pragma unroll
        for (int i = 0; i < 2; i++) {
            int cid = tid + (i << 8);
            int r = cid >> 2, c = cid & 3;
            uint32_t soff = (uint32_t)(r << 6) + (uint32_t)((c ^ ((r >> 1) & 3)) << 4);
            int arow = bm + r;
            const char* ga = (const char*)(Abase + (size_t)(arow < M ? arow : 0) * ldab) + (c << 4);
            cp_async16(sA + soff, ga, arow < M ? 16 : 0);
            const char* gb = (const char*)(Bbase + (size_t)(bn + r) * ldab) + (c << 4);
            cp_async16(sB + soff, gb, 16);
        }
        cp_commit();
    };

    issue_loads(0, 0);

    for (int kb = 0; kb < nk; kb++) {
        const int s = kb & 1;
        if (kb + 1 < nk) issue_loads(kb + 1, s ^ 1);
        if (kb + 1 < nk) cp_wait<1>(); else cp_wait<0>();
        __syncthreads();

        const uint32_t sA = sb + s * 16384;
        const uint32_t sB = sA + 8192;
        const int lr = lane & 15;
        const int lk = (lane >> 4) << 4;
#pragma unroll
        for (int k16 = 0; k16 < 2; k16++) {
            const int kby = (k16 << 5) + lk;
            const int csel = kby >> 4;
            uint32_t a[2][4], bf[4][4];
#pragma unroll
            for (int mt = 0; mt < 2; mt++) {
                int r = wm * 32 + mt * 16 + lr;
                uint32_t addr = sA + (uint32_t)(r << 6) + (uint32_t)((csel ^ ((r >> 1) & 3)) << 4);
                ldmatrix_x4(a[mt], addr);
            }
#pragma unroll
            for (int p = 0; p < 4; p++) {
                int r = wn * 64 + p * 16 + lr;
                uint32_t addr = sB + (uint32_t)(r << 6) + (uint32_t)((csel ^ ((r >> 1) & 3)) << 4);
                ldmatrix_x4(bf[p], addr);
            }
#pragma unroll
            for (int mt = 0; mt < 2; mt++)
#pragma unroll
                for (int nt = 0; nt < 8; nt++) {
                    int p = nt >> 1, hi = nt & 1;
                    mma16816(d[mt][nt], a[mt], bf[p][hi], bf[p][2 + hi]);
                }
        }
        __syncthreads();
    }

    const int gr = lane >> 2;
    const int gc = (lane & 3) << 1;
#pragma unroll
    for (int mt = 0; mt < 2; mt++) {
        int r0 = bm + wm * 32 + mt * 16 + gr;
#pragma unroll
        for (int nt = 0; nt < 8; nt++) {
            int cc = bn + wn * 64 + nt * 8 + gc;
            if (r0 < M)
                *(float2*)(C + (size_t)r0 * Nc + cc) = make_float2(d[mt][nt][0], d[mt][nt][1]);
            if (r0 + 8 < M)
                *(float2*)(C + (size_t)(r0 + 8) * Nc + cc) = make_float2(d[mt][nt][2], d[mt][nt][3]);
        }
    }
}

// ---------------- fused recurrent step: gh GEMM + GRU cell ----------------
// hbin [M,256] bf16 hi|lo, Wint [384,256] bf16 gate-interleaved rows (3u+g),
// gi [M*TT*G3] fp32 gate-interleaved cols. Tile 128 rows x 96 gate-cols
// (= 32 hidden units), K logical 384 (3 segs x 128) in 6 chunks of 64.
// Epilogue: smem transpose + full gate math; writes h fp32, hbout split, o0b.
// grid = (4, ceil(M/128)), 256 threads, dyn smem 57344.
__global__ void __launch_bounds__(256) gru_step_k(
    const __nv_bfloat16* __restrict__ hbin,
    __nv_bfloat16* __restrict__ hbout,
    const __nv_bfloat16* __restrict__ Wint,
    const float* __restrict__ gi,
    const float* __restrict__ bih, const float* __restrict__ bhh,
    float* __restrict__ h,
    __nv_bfloat16* __restrict__ o0b,
    int t, int M)
{
    extern __shared__ __align__(16) char smem[];
    const uint32_t sb = smem_u32(smem);
    const int tid = threadIdx.x;
    const int wid = tid >> 5, lane = tid & 31;
    const int wm = wid & 3;          // 4 row groups of 32
    const int wn = wid >> 2;         // 2 col groups of 48
    const int bm = blockIdx.y * 128;
    const int bn = blockIdx.x * 96;  // gate-col tile base

    float d[2][6][4];
#pragma unroll
    for (int i = 0; i < 2; i++)
#pragma unroll
        for (int j = 0; j < 6; j++)
#pragma unroll
            for (int q = 0; q < 4; q++) d[i][j][q] = 0.f;

    // stage: A 128x128B = 16384, B 96x128B = 12288 -> 28672 per stage
    auto issue = [&](int kb, int s) {
        const int seg = kb >> 1, kc = kb & 1;
        const int acol = (seg == 1 ? HH : 0) + (kc << 6);
        const int bcol = (seg == 2 ? HH : 0) + (kc << 6);
        const uint32_t sA = sb + s * 28672;
        const uint32_t sB = sA + 16384;
#pragma unroll
        for (int i = 0; i < 4; i++) {            // A: 1024 chunks of 16B
            int cid = tid + (i << 8);
            int r = cid >> 3, c = cid & 7;
            uint32_t soff = (uint32_t)(r << 7) + (uint32_t)((c ^ ((r >> 1) & 7)) << 4);
            int arow = bm + r;
            const char* ga = (const char*)(hbin + (size_t)(arow < M ? arow : 0) * 256 + acol) + (c << 4);
            cp_async16(sA + soff, ga, arow < M ? 16 : 0);
        }
#pragma unroll
        for (int i = 0; i < 3; i++) {            // B: 768 chunks
            int cid = tid + (i << 8);
            int r = cid >> 3, c = cid & 7;
            uint32_t soff = (uint32_t)(r << 7) + (uint32_t)((c ^ ((r >> 1) & 7)) << 4);
            const char* gb = (const char*)(Wint + (size_t)(bn + r) * 256 + bcol) + (c << 4);
            cp_async16(sB + soff, gb, 16);
        }
        cp_commit();
    };

    issue(0, 0);

    for (int kb = 0; kb < 6; kb++) {
        const int s = kb & 1;
        if (kb < 5) issue(kb + 1, s ^ 1);
        if (kb < 5) cp_wait<1>(); else cp_wait<0>();
        __syncthreads();

        const uint32_t sA = sb + s * 28672;
        const uint32_t sB = sA + 16384;
        const int lr = lane & 15;
        const int lkc = lane >> 4;               // 0/1: second 16B (k+8) half
#pragma unroll
        for (int k16 = 0; k16 < 4; k16++) {
            const int csel = (k16 << 1) + lkc;   // 16B chunk index 0..7
            uint32_t a[2][4], bf[3][4];
#pragma unroll
            for (int mt = 0; mt < 2; mt++) {
                int r = wm * 32 + mt * 16 + lr;
                uint32_t addr = sA + (uint32_t)(r << 7) + (uint32_t)((csel ^ ((r >> 1) & 7)) << 4);
                ldmatrix_x4(a[mt], addr);
            }
#pragma unroll
            for (int p = 0; p < 3; p++) {
                int r = wn * 48 + p * 16 + lr;
                uint32_t addr = sB + (uint32_t)(r << 7) + (uint32_t)((csel ^ ((r >> 1) & 7)) << 4);
                ldmatrix_x4(bf[p], addr);
            }
#pragma unroll
            for (int mt = 0; mt < 2; mt++)
#pragma unroll
                for (int nt = 0; nt < 6; nt++) {
                    int p = nt >> 1, hi = nt & 1;
                    mma16816(d[mt][nt], a[mt], bf[p][hi], bf[p][2 + hi]);
                }
        }
        __syncthreads();
    }

    // ---- epilogue: dump 128x96 gh tile to smem (pitch 100) ----
    float* ssm = (float*)smem;
    const int gr = lane >> 2;
    const int gc = (lane & 3) << 1;
#pragma unroll
    for (int mt = 0; mt < 2; mt++) {
        int r0 = wm * 32 + mt * 16 + gr;
#pragma unroll
        for (int nt = 0; nt < 6; nt++) {
            int cc = wn * 48 + nt * 8 + gc;
            ssm[r0 * 100 + cc]           = d[mt][nt][0];
            ssm[r0 * 100 + cc + 1]       = d[mt][nt][1];
            ssm[(r0 + 8) * 100 + cc]     = d[mt][nt][2];
            ssm[(r0 + 8) * 100 + cc + 1] = d[mt][nt][3];
        }
    }
    __syncthreads();

    // ---- gate math: warp = 16 rows, lane = hidden unit 0..31 ----
    const int u = lane;
    const int ug = (bn / 3) + u;                 // global hidden unit
    const float br = bih[ug],        bz = bih[HH + ug],      bn_ = bih[2 * HH + ug];
    const float cr = bhh[ug],        cz = bhh[HH + ug],      cn  = bhh[2 * HH + ug];
    for (int rr = 0; rr < 16; rr++) {
        int r = wid * 16 + rr;
        int ig = bm + r;
        if (ig >= M) break;
        float ghr = ssm[r * 100 + 3 * u];
        float ghz = ssm[r * 100 + 3 * u + 1];
        float ghn = ssm[r * 100 + 3 * u + 2];
        size_t gbase = ((size_t)ig * TT + t) * G3 + bn + 3 * u;
        float gir = gi[gbase], giz = gi[gbase + 1], gin = gi[gbase + 2];
        float rg = 1.f / (1.f + expf(-(gir + br + ghr + cr)));
        float z  = 1.f / (1.f + expf(-(giz + bz + ghz + cz)));
        float n  = tanhf(gin + bn_ + rg * (ghn + cn));
        float hold = h[(size_t)ig * HH + ug];
        float hnew = (1.f - z) * n + z * hold;
        h[(size_t)ig * HH + ug] = hnew;
        __nv_bfloat16 hi = __float2bfloat16(hnew);
        __nv_bfloat16 lo = __float2bfloat16(hnew - __bfloat162float(hi));
        hbout[(size_t)ig * 256 + ug]      = hi;
        hbout[(size_t)ig * 256 + HH + ug] = lo;
        if (o0b) {
            size_t ro = ((size_t)ig * TT + t) * 256;
            o0b[ro + ug]      = hi;
            o0b[ro + HH + ug] = lo;
        }
    }
}

// ---------------- GAT kernels ----------------
__global__ void gat_scores_k(const float* __restrict__ hlin,
                             const float* __restrict__ asrc, const float* __restrict__ adst,
                             float* __restrict__ es, float* __restrict__ ed,
                             unsigned* __restrict__ mu, int n) {
    int g = blockIdx.x * blockDim.x + threadIdx.x;
    int node = g >> 5;
    int lane = g & 31;
    if (node >= n) return;
    float4 h4 = reinterpret_cast<const float4*>(hlin + (size_t)node * HH)[lane];
    float4 a4 = reinterpret_cast<const float4*>(asrc)[lane];
    float4 d4 = reinterpret_cast<const float4*>(adst)[lane];
    float s = h4.x * a4.x + h4.y * a4.y + h4.z * a4.z + h4.w * a4.w;
    float d = h4.x * d4.x + h4.y * d4.y + h4.z * d4.z + h4.w * d4.w;
#pragma unroll
    for (int o = 16; o; o >>= 1) {
        s += __shfl_xor_sync(0xffffffffu, s, o);
        d += __shfl_xor_sync(0xffffffffu, d, o);
    }
    if (lane == 0) {
        es[node] = s;
        ed[node] = d;
        mu[node] = fkey(lrelu(s + d));
    }
}

__global__ void gat_edge_max_k(const int* __restrict__ ei,
                               const float* __restrict__ es, const float* __restrict__ ed,
                               float* __restrict__ eedge, unsigned* __restrict__ mu, int E) {
    int e = blockIdx.x * blockDim.x + threadIdx.x;
    if (e >= E) return;
    int s = ei[e];
    int d = ei[E + e];
    float v = lrelu(es[s] + ed[d]);
    eedge[e] = v;
    atomicMax(&mu[d], fkey(v));
}

__global__ void gat_node_init_k(const float* __restrict__ hlin,
                                const float* __restrict__ es, const float* __restrict__ ed,
                                const unsigned* __restrict__ mu,
                                float* __restrict__ m, float* __restrict__ den,
                                float* __restrict__ acc) {
    int i = blockIdx.x;
    int j = threadIdx.x;
    float mv = funkey(mu[i]);
    float w0 = expf(lrelu(es[i] + ed[i]) - mv);
    if (j == 0) { m[i] = mv; den[i] = w0; }
    acc[(size_t)i * HH + j] = w0 * hlin[(size_t)i * HH + j];
}

__global__ void gat_edge_agg_k(const int* __restrict__ ei, const float* __restrict__ eedge,
                               const float* __restrict__ m, const float* __restrict__ hlin,
                               float* __restrict__ den, float* __restrict__ acc, int E) {
    int g = blockIdx.x * blockDim.x + threadIdx.x;
    int e = g >> 5;
    int lane = g & 31;
    if (e >= E) return;
    int s = ei[e];
    int d = ei[E + e];
    float w = expf(eedge[e] - m[d]);
    if (lane == 0) atomicAdd(&den[d], w);
    float4 hv = reinterpret_cast<const float4*>(hlin + (size_t)s * HH)[lane];
    float* ap = acc + (size_t)d * HH + 4 * lane;
    atomicAdd(ap + 0, w * hv.x);
    atomicAdd(ap + 1, w * hv.y);
    atomicAdd(ap + 2, w * hv.z);
    atomicAdd(ap + 3, w * hv.w);
}

__global__ void gat_finalize_k(float* __restrict__ acc, const float* __restrict__ den,
                               const float* __restrict__ bias) {
    int i = blockIdx.x;
    int j = threadIdx.x;
    acc[(size_t)i * HH + j] = acc[(size_t)i * HH + j] / den[i] + bias[j];
}

// ---------------- sector max pool ----------------
__global__ void pool_max_k(const float* __restrict__ x, const int* __restrict__ sid,
                           unsigned* __restrict__ pu) {
    int idx = blockIdx.x * blockDim.x + threadIdx.x;
    if (idx >= NN * HH) return;
    int i = idx >> 7;
    int j = idx & 127;
    atomicMax(&pu[sid[i] * HH + j], fkey(x[idx]));
}
__global__ void pool_conv_k(const unsigned* __restrict__ pu, float* __restrict__ p,
                            __nv_bfloat16* __restrict__ pb) {
    int idx = blockIdx.x * blockDim.x + threadIdx.x;
    if (idx >= SS * HH) return;
    int r = idx >> 7, j = idx & 127;
    float v = funkey(pu[idx]);
    p[idx] = v;
    __nv_bfloat16 hi = __float2bfloat16(v);
    __nv_bfloat16 lo = __float2bfloat16(v - __bfloat162float(hi));
    pb[(size_t)r * 2 * HH + j]      = hi;
    pb[(size_t)r * 2 * HH + HH + j] = lo;
}

// ---------------- fusion head ----------------
__global__ void fusion_k(const float* __restrict__ seq, const float* __restrict__ intra,
                         const float* __restrict__ inter, const int* __restrict__ sid,
                         const float* __restrict__ fw, const float* __restrict__ fb,
                         float* __restrict__ out) {
    int g = blockIdx.x * blockDim.x + threadIdx.x;
    int i = g >> 5;
    int lane = g & 31;
    if (i >= NN) return;
    int sc = sid[i];
    const float4* s4 = reinterpret_cast<const float4*>(seq + (size_t)i * HH);
    const float4* i4 = reinterpret_cast<const float4*>(intra + (size_t)i * HH);
    const float4* e4 = reinterpret_cast<const float4*>(inter + (size_t)sc * HH);
    const float4* w4 = reinterpret_cast<const float4*>(fw);
    float sum = 0.f;
    float4 a, b;
    a = s4[lane]; b = w4[lane];
    sum += a.x * b.x + a.y * b.y + a.z * b.z + a.w * b.w;
    a = i4[lane]; b = w4[32 + lane];
    sum += a.x * b.x + a.y * b.y + a.z * b.z + a.w * b.w;
    a = e4[lane]; b = w4[64 + lane];
    sum += a.x * b.x + a.y * b.y + a.z * b.z + a.w * b.w;
#pragma unroll
    for (int o = 16; o; o >>= 1) sum += __shfl_xor_sync(0xffffffffu, sum, o);
    if (lane == 0) out[i] = sum + fb[0];
}

// ---------------- host ----------------
#define STEP_SMEM 57344

static inline void launch_gemm(const __nv_bfloat16* Ab, const __nv_bfloat16* Bb,
                               float* C, int M, int Nc, int K) {
    dim3 grid(Nc / 128, (M + 127) / 128);
    gemm_mma_k<<<grid, 256>>>(Ab, Bb, C, M, Nc, K);
}

extern "C" void kernel_launch(void* const* d_in, const int* in_sizes, int n_in,
                              void* d_out, int out_size) {
    const float* x        = (const float*)d_in[0];
    const int*   ei_intra = (const int*)d_in[1];
    const int*   ei_inter = (const int*)d_in[2];
    const int*   sid      = (const int*)d_in[3];
    const float* w_ih0 = (const float*)d_in[4];
    const float* w_hh0 = (const float*)d_in[5];
    const float* b_ih0 = (const float*)d_in[6];
    const float* b_hh0 = (const float*)d_in[7];
    const float* w_ih1 = (const float*)d_in[8];
    const float* w_hh1 = (const float*)d_in[9];
    const float* b_ih1 = (const float*)d_in[10];
    const float* b_hh1 = (const float*)d_in[11];
    const float* intra_W  = (const float*)d_in[12];
    const float* a_src_i  = (const float*)d_in[13];
    const float* a_dst_i  = (const float*)d_in[14];
    const float* bias_i   = (const float*)d_in[15];
    const float* inter_W  = (const float*)d_in[16];
    const float* a_src_e  = (const float*)d_in[17];
    const float* a_dst_e  = (const float*)d_in[18];
    const float* bias_e   = (const float*)d_in[19];
    const float* fw       = (const float*)d_in[20];
    const float* fb       = (const float*)d_in[21];
    float* out = (float*)d_out;

    cudaFuncSetAttribute(gru_step_k, cudaFuncAttributeMaxDynamicSharedMemorySize, STEP_SMEM);

    float *gi, *h, *hlin, *acc, *es, *ed, *m, *den, *eedge, *pool, *shlin, *sacc;
    __nv_bfloat16 *xb, *o0b, *hbA, *hbB, *wb_ih0, *wb_hh0, *wb_ih1, *wb_hh1, *wb_a, *wb_e, *poolb;
    unsigned *mu, *pu;
    cudaGetSymbolAddress((void**)&gi, g_gi);
    cudaGetSymbolAddress((void**)&xb, g_xb);
    cudaGetSymbolAddress((void**)&o0b, g_o0b);
    cudaGetSymbolAddress((void**)&h, g_h);
    cudaGetSymbolAddress((void**)&hbA, g_hbA);
    cudaGetSymbolAddress((void**)&hbB, g_hbB);
    cudaGetSymbolAddress((void**)&hlin, g_hlin);
    cudaGetSymbolAddress((void**)&acc, g_acc);
    cudaGetSymbolAddress((void**)&wb_ih0, g_wb_ih0);
    cudaGetSymbolAddress((void**)&wb_hh0, g_wb_hh0);
    cudaGetSymbolAddress((void**)&wb_ih1, g_wb_ih1);
    cudaGetSymbolAddress((void**)&wb_hh1, g_wb_hh1);
    cudaGetSymbolAddress((void**)&wb_a, g_wb_intra);
    cudaGetSymbolAddress((void**)&wb_e, g_wb_inter);
    cudaGetSymbolAddress((void**)&es, g_es);
    cudaGetSymbolAddress((void**)&ed, g_ed);
    cudaGetSymbolAddress((void**)&m, g_m);
    cudaGetSymbolAddress((void**)&den, g_den);
    cudaGetSymbolAddress((void**)&mu, g_mu);
    cudaGetSymbolAddress((void**)&eedge, g_eedge);
    cudaGetSymbolAddress((void**)&pu, g_pu);
    cudaGetSymbolAddress((void**)&pool, g_pool);
    cudaGetSymbolAddress((void**)&poolb, g_poolb);
    cudaGetSymbolAddress((void**)&shlin, g_shlin);
    cudaGetSymbolAddress((void**)&sacc, g_sacc);

    const dim3 stepGrid(4, (NN + 127) / 128);

    // ---- GRU layer 0 ----
    convw_int_k<<<(G3 * INP + 255) / 256, 256>>>(w_ih0, wb_ih0, INP);
    convw_k<<<(NN * TT * INP + 255) / 256, 256>>>(x, xb, NN * TT, INP);
    launch_gemm(xb, wb_ih0, gi, NN * TT, G3, INP);     // gi gate-interleaved
    convw_int_k<<<(G3 * HH + 255) / 256, 256>>>(w_hh0, wb_hh0, HH);
    zerof_k<<<(NN * HH + 255) / 256, 256>>>(h, NN * HH);
    zerou_k<<<(NN * HH + 255) / 256, 256>>>((unsigned*)hbA, NN * HH);
    {
        __nv_bfloat16* cur = hbA;
        __nv_bfloat16* nxt = hbB;
        for (int t = 0; t < TT; t++) {
            gru_step_k<<<stepGrid, 256, STEP_SMEM>>>(cur, nxt, wb_hh0, gi,
                                                     b_ih0, b_hh0, h, o0b, t, NN);
            __nv_bfloat16* tmp = cur; cur = nxt; nxt = tmp;
        }
    }

    // ---- GRU layer 1 ----
    convw_int_k<<<(G3 * HH + 255) / 256, 256>>>(w_ih1, wb_ih1, HH);
    launch_gemm(o0b, wb_ih1, gi, NN * TT, G3, HH);
    convw_int_k<<<(G3 * HH + 255) / 256, 256>>>(w_hh1, wb_hh1, HH);
    zerof_k<<<(NN * HH + 255) / 256, 256>>>(h, NN * HH);
    zerou_k<<<(NN * HH + 255) / 256, 256>>>((unsigned*)hbA, NN * HH);
    __nv_bfloat16* hbFinal;
    {
        __nv_bfloat16* cur = hbA;
        __nv_bfloat16* nxt = hbB;
        for (int t = 0; t < TT; t++) {
            gru_step_k<<<stepGrid, 256, STEP_SMEM>>>(cur, nxt, wb_hh1, gi,
                                                     b_ih1, b_hh1, h, nullptr, t, NN);
            __nv_bfloat16* tmp = cur; cur = nxt; nxt = tmp;
        }
        hbFinal = cur;   // after even TT swaps, cur == hbA (holds final state)
    }
    // h == seq_emb (fp32), hbFinal == its bf16 split

    // ---- intra GAT ----
    convw_k<<<(HH * HH + 255) / 256, 256>>>(intra_W, wb_a, HH, HH);
    launch_gemm(hbFinal, wb_a, hlin, NN, HH, HH);
    gat_scores_k<<<(NN * 32 + 255) / 256, 256>>>(hlin, a_src_i, a_dst_i, es, ed, mu, NN);
    gat_edge_max_k<<<(EINTRA + 255) / 256, 256>>>(ei_intra, es, ed, eedge, mu, EINTRA);
    gat_node_init_k<<<NN, HH>>>(hlin, es, ed, mu, m, den, acc);
    gat_edge_agg_k<<<(EINTRA * 32 + 255) / 256, 256>>>(ei_intra, eedge, m, hlin, den, acc, EINTRA);
    gat_finalize_k<<<NN, HH>>>(acc, den, bias_i);
    // acc == intra_emb

    // ---- sector max pool ----
    zerou_k<<<(SS * HH + 255) / 256, 256>>>(pu, SS * HH);
    pool_max_k<<<(NN * HH + 255) / 256, 256>>>(acc, sid, pu);
    pool_conv_k<<<(SS * HH + 255) / 256, 256>>>(pu, pool, poolb);

    // ---- inter GAT (S=64) ----
    convw_k<<<(HH * HH + 255) / 256, 256>>>(inter_W, wb_e, HH, HH);
    launch_gemm(poolb, wb_e, shlin, SS, HH, HH);
    gat_scores_k<<<(SS * 32 + 255) / 256, 256>>>(shlin, a_src_e, a_dst_e, es, ed, mu, SS);
    gat_edge_max_k<<<(EINTER + 255) / 256, 256>>>(ei_inter, es, ed, eedge, mu, EINTER);
    gat_node_init_k<<<SS, HH>>>(shlin, es, ed, mu, m, den, sacc);
    gat_edge_agg_k<<<(EINTER * 32 + 255) / 256, 256>>>(ei_inter, eedge, m, shlin, den, sacc, EINTER);
    gat_finalize_k<<<SS, HH>>>(sacc, den, bias_e);
    // sacc == inter_sec

    // ---- fusion ----
    fusion_k<<<(NN * 32 + 255) / 256, 256>>>(h, acc, sacc, sid, fw, fb, out);
}

// round 7
// speedup vs baseline: 1.0119x; 1.0119x over previous
#include <cuda_runtime.h>
#include <cuda_bf16.h>
#include <math.h>
#include <stdint.h>

#define NN     20000
#define TT     32
#define INP    64
#define HH     128
#define G3     384
#define SS     64
#define EINTRA 640000
#define EINTER 4096

// ---------------- scratch (static device globals; no allocs) ----------------
__device__ __align__(128) float g_gi[(size_t)NN*TT*G3];            // 983 MB (gate-interleaved cols)
__device__ __align__(128) __nv_bfloat16 g_xb[(size_t)NN*TT*2*INP]; // x as hi|lo
__device__ __align__(128) __nv_bfloat16 g_o0b[(size_t)NN*TT*2*HH]; // layer0 outputs hi|lo
__device__ __align__(128) float g_h[(size_t)NN*HH];
__device__ __align__(128) __nv_bfloat16 g_hbA[(size_t)NN*2*HH];
__device__ __align__(128) __nv_bfloat16 g_hbB[(size_t)NN*2*HH];
__device__ __align__(128) float g_hlin[(size_t)NN*HH];
__device__ __align__(128) float g_acc[(size_t)NN*HH];
__device__ __align__(128) __nv_bfloat16 g_wb_ih0[G3*2*INP];   // gate-interleaved rows
__device__ __align__(128) __nv_bfloat16 g_wb_hh0[G3*2*HH];    // gate-interleaved rows
__device__ __align__(128) __nv_bfloat16 g_wb_ih1[G3*2*HH];    // gate-interleaved rows
__device__ __align__(128) __nv_bfloat16 g_wb_hh1[G3*2*HH];    // gate-interleaved rows
__device__ __align__(128) __nv_bfloat16 g_wb_intra[HH*2*HH];
__device__ __align__(128) __nv_bfloat16 g_wb_inter[HH*2*HH];
__device__ float    g_es[NN];
__device__ float    g_ed[NN];
__device__ float    g_m[NN];
__device__ float    g_den[NN];
__device__ unsigned g_mu[NN];
__device__ float    g_eedge[EINTRA];
__device__ unsigned g_pu[SS*HH];
__device__ __align__(128) float g_pool[SS*HH];
__device__ __align__(128) __nv_bfloat16 g_poolb[SS*2*HH];
__device__ __align__(128) float g_shlin[SS*HH];
__device__ __align__(128) float g_sacc[SS*HH];

// ---------------- helpers ----------------
__device__ __forceinline__ uint32_t smem_u32(const void* p) {
    uint32_t a;
    asm("{ .reg .u64 t; cvta.to.shared.u64 t, %1; cvt.u32.u64 %0, t; }" : "=r"(a) : "l"(p));
    return a;
}
__device__ __forceinline__ unsigned fkey(float f) {
    unsigned u = __float_as_uint(f);
    return (u & 0x80000000u) ? ~u : (u | 0x80000000u);
}
__device__ __forceinline__ float funkey(unsigned k) {
    return (k & 0x80000000u) ? __uint_as_float(k & 0x7fffffffu)
                             : __uint_as_float(~k);
}
__device__ __forceinline__ float lrelu(float x) { return x > 0.f ? x : 0.2f * x; }

__device__ __forceinline__ void cp_async16(uint32_t saddr, const void* gaddr, int srcBytes) {
    asm volatile("cp.async.cg.shared.global [%0], [%1], 16, %2;"
                 :: "r"(saddr), "l"(gaddr), "r"(srcBytes) : "memory");
}
__device__ __forceinline__ void cp_commit() {
    asm volatile("cp.async.commit_group;" ::: "memory");
}
template <int N>
__device__ __forceinline__ void cp_wait() {
    asm volatile("cp.async.wait_group %0;" :: "n"(N) : "memory");
}
__device__ __forceinline__ void ldmatrix_x4(uint32_t* r, uint32_t addr) {
    asm volatile("ldmatrix.sync.aligned.m8n8.x4.shared.b16 {%0,%1,%2,%3}, [%4];"
                 : "=r"(r[0]), "=r"(r[1]), "=r"(r[2]), "=r"(r[3]) : "r"(addr));
}
__device__ __forceinline__ void mma16816(float* d, const uint32_t* a, uint32_t b0, uint32_t b1) {
    asm volatile(
        "mma.sync.aligned.m16n8k16.row.col.f32.bf16.bf16.f32 "
        "{%0,%1,%2,%3}, {%4,%5,%6,%7}, {%8,%9}, {%0,%1,%2,%3};"
        : "+f"(d[0]), "+f"(d[1]), "+f"(d[2]), "+f"(d[3])
        : "r"(a[0]), "r"(a[1]), "r"(a[2]), "r"(a[3]), "r"(b0), "r"(b1));
}

// ---------------- misc kernels ----------------
__global__ void zerof_k(float* p, int n) {
    int i = blockIdx.x * blockDim.x + threadIdx.x;
    if (i < n) p[i] = 0.f;
}
__global__ void zerou_k(unsigned* p, int n) {
    int i = blockIdx.x * blockDim.x + threadIdx.x;
    if (i < n) p[i] = 0u;
}
// split fp32 [rows,K] -> bf16 [rows, 2K] as [hi | lo]
__global__ void convw_k(const float* __restrict__ W, __nv_bfloat16* __restrict__ Wb,
                        int rows, int K) {
    int idx = blockIdx.x * blockDim.x + threadIdx.x;
    if (idx >= rows * K) return;
    int r = idx / K, c = idx % K;
    float v = W[idx];
    __nv_bfloat16 hi = __float2bfloat16(v);
    __nv_bfloat16 lo = __float2bfloat16(v - __bfloat162float(hi));
    Wb[(size_t)r * 2 * K + c]     = hi;
    Wb[(size_t)r * 2 * K + K + c] = lo;
}
// GRU weight conv with gate interleave: out row 3u+g <- in row g*128+u. W [384,K].
__global__ void convw_int_k(const float* __restrict__ W, __nv_bfloat16* __restrict__ Wb, int K) {
    int idx = blockIdx.x * blockDim.x + threadIdx.x;
    if (idx >= G3 * K) return;
    int rr = idx / K, c = idx % K;
    int u = rr / 3, g = rr % 3;
    float v = W[(size_t)(g * HH + u) * K + c];
    __nv_bfloat16 hi = __float2bfloat16(v);
    __nv_bfloat16 lo = __float2bfloat16(v - __bfloat162float(hi));
    Wb[(size_t)rr * 2 * K + c]     = hi;
    Wb[(size_t)rr * 2 * K + K + c] = lo;
}

// ---------------- tensor-core GEMM (mma.sync bf16): C = split(A) @ split(B)^T ----
// Ab [M, 2K] bf16 (hi|lo), Bb [Nc, 2K] bf16 (hi|lo), C [M,Nc] fp32.
// Computes Ahi@Bhi^T + Alo@Bhi^T + Ahi@Blo^T. Tile 128x128xBK32, cp.async
// double buffer, XOR-swizzled smem, 8 warps each 32x64.
// grid = (Nc/128, ceil(M/128)); Nc % 128 == 0; K % 32 == 0.
__global__ void __launch_bounds__(256) gemm_mma_k(
    const __nv_bfloat16* __restrict__ Ab,
    const __nv_bfloat16* __restrict__ Bb,
    float* __restrict__ C, int M, int Nc, int K)
{
    __shared__ __align__(16) char smbuf[32768];  // [2 stages][A 8K | B 8K]
    const uint32_t sb = smem_u32(smbuf);
    const int tid = threadIdx.x;
    const int wid = tid >> 5, lane = tid & 31;
    const int wm = wid & 3;          // warp row  (32 rows)
    const int wn = wid >> 2;         // warp col  (64 cols)
    const int bm = blockIdx.y * 128;
    const int bn = blockIdx.x * 128;
    const int ldab = 2 * K;          // bf16 elems per row of Ab/Bb

    const int cpk = K >> 5;          // 32-elem chunks per K segment
    const int nk = 3 * cpk;

    float d[2][8][4];
#pragma unroll
    for (int i = 0; i < 2; i++)
#pragma unroll
        for (int j = 0; j < 8; j++)
#pragma unroll
            for (int q = 0; q < 4; q++) d[i][j][q] = 0.f;

    auto issue_loads = [&](int kb, int s) {
        const int seg = kb / cpk, kc = kb - seg * cpk;
        const int acol = (seg == 1 ? K : 0) + (kc << 5);
        const int bcol = (seg == 2 ? K : 0) + (kc << 5);
        const __nv_bfloat16* Abase = Ab + acol;
        const __nv_bfloat16* Bbase = Bb + bcol;
        const uint32_t sA = sb + s * 16384;
        const uint32_t sB = sA + 8192;
#pragma unroll
        for (int i = 0; i < 2; i++) {
            int cid = tid + (i << 8);
            int r = cid >> 2, c = cid & 3;
            uint32_t soff = (uint32_t)(r << 6) + (uint32_t)((c ^ ((r >> 1) & 3)) << 4);
            int arow = bm + r;
            const char* ga = (const char*)(Abase + (size_t)(arow < M ? arow : 0) * ldab) + (c << 4);
            cp_async16(sA + soff, ga, arow < M ? 16 : 0);
            const char* gb = (const char*)(Bbase + (size_t)(bn + r) * ldab) + (c << 4);
            cp_async16(sB + soff, gb, 16);
        }
        cp_commit();
    };

    issue_loads(0, 0);

    for (int kb = 0; kb < nk; kb++) {
        const int s = kb & 1;
        if (kb + 1 < nk) issue_loads(kb + 1, s ^ 1);
        if (kb + 1 < nk) cp_wait<1>(); else cp_wait<0>();
        __syncthreads();

        const uint32_t sA = sb + s * 16384;
        const uint32_t sB = sA + 8192;
        const int lr = lane & 15;
        const int lk = (lane >> 4) << 4;
#pragma unroll
        for (int k16 = 0; k16 < 2; k16++) {
            const int kby = (k16 << 5) + lk;
            const int csel = kby >> 4;
            uint32_t a[2][4], bf[4][4];
#pragma unroll
            for (int mt = 0; mt < 2; mt++) {
                int r = wm * 32 + mt * 16 + lr;
                uint32_t addr = sA + (uint32_t)(r << 6) + (uint32_t)((csel ^ ((r >> 1) & 3)) << 4);
                ldmatrix_x4(a[mt], addr);
            }
#pragma unroll
            for (int p = 0; p < 4; p++) {
                int r = wn * 64 + p * 16 + lr;
                uint32_t addr = sB + (uint32_t)(r << 6) + (uint32_t)((csel ^ ((r >> 1) & 3)) << 4);
                ldmatrix_x4(bf[p], addr);
            }
#pragma unroll
            for (int mt = 0; mt < 2; mt++)
#pragma unroll
                for (int nt = 0; nt < 8; nt++) {
                    int p = nt >> 1, hi = nt & 1;
                    mma16816(d[mt][nt], a[mt], bf[p][hi], bf[p][2 + hi]);
                }
        }
        __syncthreads();
    }

    const int gr = lane >> 2;
    const int gc = (lane & 3) << 1;
#pragma unroll
    for (int mt = 0; mt < 2; mt++) {
        int r0 = bm + wm * 32 + mt * 16 + gr;
#pragma unroll
        for (int nt = 0; nt < 8; nt++) {
            int cc = bn + wn * 64 + nt * 8 + gc;
            if (r0 < M)
                *(float2*)(C + (size_t)r0 * Nc + cc) = make_float2(d[mt][nt][0], d[mt][nt][1]);
            if (r0 + 8 < M)
                *(float2*)(C + (size_t)(r0 + 8) * Nc + cc) = make_float2(d[mt][nt][2], d[mt][nt][3]);
        }
    }
}

// ---------------- fused recurrent step: gh GEMM + GRU cell ----------------
// hbin [M,256] bf16 hi|lo, Wint [384,256] bf16 gate-interleaved rows (3u+g),
// gi [M*TT*G3] fp32 gate-interleaved cols. Tile 128 rows x 96 gate-cols
// (= 32 hidden units), K logical 384 (3 segs x 128) in 6 chunks of 64.
// Epilogue: smem transpose + full gate math; writes h fp32, hbout split, o0b.
// grid = (4, ceil(M/128)), 256 threads, dyn smem 57344.
__global__ void __launch_bounds__(256) gru_step_k(
    const __nv_bfloat16* __restrict__ hbin,
    __nv_bfloat16* __restrict__ hbout,
    const __nv_bfloat16* __restrict__ Wint,
    const float* __restrict__ gi,
    const float* __restrict__ bih, const float* __restrict__ bhh,
    float* __restrict__ h,
    __nv_bfloat16* __restrict__ o0b,
    int t, int M)
{
    extern __shared__ __align__(16) char smem[];
    const uint32_t sb = smem_u32(smem);
    const int tid = threadIdx.x;
    const int wid = tid >> 5, lane = tid & 31;
    const int wm = wid & 3;          // 4 row groups of 32
    const int wn = wid >> 2;         // 2 col groups of 48
    const int bm = blockIdx.y * 128;
    const int bn = blockIdx.x * 96;  // gate-col tile base

    float d[2][6][4];
#pragma unroll
    for (int i = 0; i < 2; i++)
#pragma unroll
        for (int j = 0; j < 6; j++)
#pragma unroll
            for (int q = 0; q < 4; q++) d[i][j][q] = 0.f;

    // stage: A 128x128B = 16384, B 96x128B = 12288 -> 28672 per stage
    auto issue = [&](int kb, int s) {
        const int seg = kb >> 1, kc = kb & 1;
        const int acol = (seg == 1 ? HH : 0) + (kc << 6);
        const int bcol = (seg == 2 ? HH : 0) + (kc << 6);
        const uint32_t sA = sb + s * 28672;
        const uint32_t sB = sA + 16384;
#pragma unroll
        for (int i = 0; i < 4; i++) {            // A: 1024 chunks of 16B
            int cid = tid + (i << 8);
            int r = cid >> 3, c = cid & 7;
            uint32_t soff = (uint32_t)(r << 7) + (uint32_t)((c ^ ((r >> 1) & 7)) << 4);
            int arow = bm + r;
            const char* ga = (const char*)(hbin + (size_t)(arow < M ? arow : 0) * 256 + acol) + (c << 4);
            cp_async16(sA + soff, ga, arow < M ? 16 : 0);
        }
#pragma unroll
        for (int i = 0; i < 3; i++) {            // B: 768 chunks
            int cid = tid + (i << 8);
            int r = cid >> 3, c = cid & 7;
            uint32_t soff = (uint32_t)(r << 7) + (uint32_t)((c ^ ((r >> 1) & 7)) << 4);
            const char* gb = (const char*)(Wint + (size_t)(bn + r) * 256 + bcol) + (c << 4);
            cp_async16(sB + soff, gb, 16);
        }
        cp_commit();
    };

    issue(0, 0);

    for (int kb = 0; kb < 6; kb++) {
        const int s = kb & 1;
        if (kb < 5) issue(kb + 1, s ^ 1);
        if (kb < 5) cp_wait<1>(); else cp_wait<0>();
        __syncthreads();

        const uint32_t sA = sb + s * 28672;
        const uint32_t sB = sA + 16384;
        const int lr = lane & 15;
        const int lkc = lane >> 4;               // 0/1: second 16B (k+8) half
#pragma unroll
        for (int k16 = 0; k16 < 4; k16++) {
            const int csel = (k16 << 1) + lkc;   // 16B chunk index 0..7
            uint32_t a[2][4], bf[3][4];
#pragma unroll
            for (int mt = 0; mt < 2; mt++) {
                int r = wm * 32 + mt * 16 + lr;
                uint32_t addr = sA + (uint32_t)(r << 7) + (uint32_t)((csel ^ ((r >> 1) & 7)) << 4);
                ldmatrix_x4(a[mt], addr);
            }
#pragma unroll
            for (int p = 0; p < 3; p++) {
                int r = wn * 48 + p * 16 + lr;
                uint32_t addr = sB + (uint32_t)(r << 7) + (uint32_t)((csel ^ ((r >> 1) & 7)) << 4);
                ldmatrix_x4(bf[p], addr);
            }
#pragma unroll
            for (int mt = 0; mt < 2; mt++)
#pragma unroll
                for (int nt = 0; nt < 6; nt++) {
                    int p = nt >> 1, hi = nt & 1;
                    mma16816(d[mt][nt], a[mt], bf[p][hi], bf[p][2 + hi]);
                }
        }
        __syncthreads();
    }

    // ---- epilogue: dump 128x96 gh tile to smem (pitch 100) ----
    float* ssm = (float*)smem;
    const int gr = lane >> 2;
    const int gc = (lane & 3) << 1;
#pragma unroll
    for (int mt = 0; mt < 2; mt++) {
        int r0 = wm * 32 + mt * 16 + gr;
#pragma unroll
        for (int nt = 0; nt < 6; nt++) {
            int cc = wn * 48 + nt * 8 + gc;
            ssm[r0 * 100 + cc]           = d[mt][nt][0];
            ssm[r0 * 100 + cc + 1]       = d[mt][nt][1];
            ssm[(r0 + 8) * 100 + cc]     = d[mt][nt][2];
            ssm[(r0 + 8) * 100 + cc + 1] = d[mt][nt][3];
        }
    }
    __syncthreads();

    // ---- gate math: warp = 16 rows, lane = hidden unit 0..31 ----
    const int u = lane;
    const int ug = (bn / 3) + u;                 // global hidden unit
    const float br = bih[ug],        bz = bih[HH + ug],      bn_ = bih[2 * HH + ug];
    const float cr = bhh[ug],        cz = bhh[HH + ug],      cn  = bhh[2 * HH + ug];
    for (int rr = 0; rr < 16; rr++) {
        int r = wid * 16 + rr;
        int ig = bm + r;
        if (ig >= M) break;
        float ghr = ssm[r * 100 + 3 * u];
        float ghz = ssm[r * 100 + 3 * u + 1];
        float ghn = ssm[r * 100 + 3 * u + 2];
        size_t gbase = ((size_t)ig * TT + t) * G3 + bn + 3 * u;
        float gir = gi[gbase], giz = gi[gbase + 1], gin = gi[gbase + 2];
        float rg = 1.f / (1.f + expf(-(gir + br + ghr + cr)));
        float z  = 1.f / (1.f + expf(-(giz + bz + ghz + cz)));
        float n  = tanhf(gin + bn_ + rg * (ghn + cn));
        float hold = h[(size_t)ig * HH + ug];
        float hnew = (1.f - z) * n + z * hold;
        h[(size_t)ig * HH + ug] = hnew;
        __nv_bfloat16 hi = __float2bfloat16(hnew);
        __nv_bfloat16 lo = __float2bfloat16(hnew - __bfloat162float(hi));
        hbout[(size_t)ig * 256 + ug]      = hi;
        hbout[(size_t)ig * 256 + HH + ug] = lo;
        if (o0b) {
            size_t ro = ((size_t)ig * TT + t) * 256;
            o0b[ro + ug]      = hi;
            o0b[ro + HH + ug] = lo;
        }
    }
}

// ---------------- GAT kernels ----------------
__global__ void gat_scores_k(const float* __restrict__ hlin,
                             const float* __restrict__ asrc, const float* __restrict__ adst,
                             float* __restrict__ es, float* __restrict__ ed,
                             unsigned* __restrict__ mu, int n) {
    int g = blockIdx.x * blockDim.x + threadIdx.x;
    int node = g >> 5;
    int lane = g & 31;
    if (node >= n) return;
    float4 h4 = reinterpret_cast<const float4*>(hlin + (size_t)node * HH)[lane];
    float4 a4 = reinterpret_cast<const float4*>(asrc)[lane];
    float4 d4 = reinterpret_cast<const float4*>(adst)[lane];
    float s = h4.x * a4.x + h4.y * a4.y + h4.z * a4.z + h4.w * a4.w;
    float d = h4.x * d4.x + h4.y * d4.y + h4.z * d4.z + h4.w * d4.w;
#pragma unroll
    for (int o = 16; o; o >>= 1) {
        s += __shfl_xor_sync(0xffffffffu, s, o);
        d += __shfl_xor_sync(0xffffffffu, d, o);
    }
    if (lane == 0) {
        es[node] = s;
        ed[node] = d;
        mu[node] = fkey(lrelu(s + d));
    }
}

__global__ void gat_edge_max_k(const int* __restrict__ ei,
                               const float* __restrict__ es, const float* __restrict__ ed,
                               float* __restrict__ eedge, unsigned* __restrict__ mu, int E) {
    int e = blockIdx.x * blockDim.x + threadIdx.x;
    if (e >= E) return;
    int s = ei[e];
    int d = ei[E + e];
    float v = lrelu(es[s] + ed[d]);
    eedge[e] = v;
    atomicMax(&mu[d], fkey(v));
}

__global__ void gat_node_init_k(const float* __restrict__ hlin,
                                const float* __restrict__ es, const float* __restrict__ ed,
                                const unsigned* __restrict__ mu,
                                float* __restrict__ m, float* __restrict__ den,
                                float* __restrict__ acc) {
    int i = blockIdx.x;
    int j = threadIdx.x;
    float mv = funkey(mu[i]);
    float w0 = expf(lrelu(es[i] + ed[i]) - mv);
    if (j == 0) { m[i] = mv; den[i] = w0; }
    acc[(size_t)i * HH + j] = w0 * hlin[(size_t)i * HH + j];
}

__global__ void gat_edge_agg_k(const int* __restrict__ ei, const float* __restrict__ eedge,
                               const float* __restrict__ m, const float* __restrict__ hlin,
                               float* __restrict__ den, float* __restrict__ acc, int E) {
    int g = blockIdx.x * blockDim.x + threadIdx.x;
    int e = g >> 5;
    int lane = g & 31;
    if (e >= E) return;
    int s = ei[e];
    int d = ei[E + e];
    float w = expf(eedge[e] - m[d]);
    if (lane == 0) atomicAdd(&den[d], w);
    float4 hv = reinterpret_cast<const float4*>(hlin + (size_t)s * HH)[lane];
    float* ap = acc + (size_t)d * HH + 4 * lane;
    atomicAdd(ap + 0, w * hv.x);
    atomicAdd(ap + 1, w * hv.y);
    atomicAdd(ap + 2, w * hv.z);
    atomicAdd(ap + 3, w * hv.w);
}

__global__ void gat_finalize_k(float* __restrict__ acc, const float* __restrict__ den,
                               const float* __restrict__ bias) {
    int i = blockIdx.x;
    int j = threadIdx.x;
    acc[(size_t)i * HH + j] = acc[(size_t)i * HH + j] / den[i] + bias[j];
}

// ---------------- sector max pool ----------------
__global__ void pool_max_k(const float* __restrict__ x, const int* __restrict__ sid,
                           unsigned* __restrict__ pu) {
    int idx = blockIdx.x * blockDim.x + threadIdx.x;
    if (idx >= NN * HH) return;
    int i = idx >> 7;
    int j = idx & 127;
    atomicMax(&pu[sid[i] * HH + j], fkey(x[idx]));
}
__global__ void pool_conv_k(const unsigned* __restrict__ pu, float* __restrict__ p,
                            __nv_bfloat16* __restrict__ pb) {
    int idx = blockIdx.x * blockDim.x + threadIdx.x;
    if (idx >= SS * HH) return;
    int r = idx >> 7, j = idx & 127;
    float v = funkey(pu[idx]);
    p[idx] = v;
    __nv_bfloat16 hi = __float2bfloat16(v);
    __nv_bfloat16 lo = __float2bfloat16(v - __bfloat162float(hi));
    pb[(size_t)r * 2 * HH + j]      = hi;
    pb[(size_t)r * 2 * HH + HH + j] = lo;
}

// ---------------- fusion head ----------------
__global__ void fusion_k(const float* __restrict__ seq, const float* __restrict__ intra,
                         const float* __restrict__ inter, const int* __restrict__ sid,
                         const float* __restrict__ fw, const float* __restrict__ fb,
                         float* __restrict__ out) {
    int g = blockIdx.x * blockDim.x + threadIdx.x;
    int i = g >> 5;
    int lane = g & 31;
    if (i >= NN) return;
    int sc = sid[i];
    const float4* s4 = reinterpret_cast<const float4*>(seq + (size_t)i * HH);
    const float4* i4 = reinterpret_cast<const float4*>(intra + (size_t)i * HH);
    const float4* e4 = reinterpret_cast<const float4*>(inter + (size_t)sc * HH);
    const float4* w4 = reinterpret_cast<const float4*>(fw);
    float sum = 0.f;
    float4 a, b;
    a = s4[lane]; b = w4[lane];
    sum += a.x * b.x + a.y * b.y + a.z * b.z + a.w * b.w;
    a = i4[lane]; b = w4[32 + lane];
    sum += a.x * b.x + a.y * b.y + a.z * b.z + a.w * b.w;
    a = e4[lane]; b = w4[64 + lane];
    sum += a.x * b.x + a.y * b.y + a.z * b.z + a.w * b.w;
#pragma unroll
    for (int o = 16; o; o >>= 1) sum += __shfl_xor_sync(0xffffffffu, sum, o);
    if (lane == 0) out[i] = sum + fb[0];
}

// ---------------- host ----------------
#define STEP_SMEM 57344

static inline void launch_gemm(const __nv_bfloat16* Ab, const __nv_bfloat16* Bb,
                               float* C, int M, int Nc, int K) {
    dim3 grid(Nc / 128, (M + 127) / 128);
    gemm_mma_k<<<grid, 256>>>(Ab, Bb, C, M, Nc, K);
}

extern "C" void kernel_launch(void* const* d_in, const int* in_sizes, int n_in,
                              void* d_out, int out_size) {
    const float* x        = (const float*)d_in[0];
    const int*   ei_intra = (const int*)d_in[1];
    const int*   ei_inter = (const int*)d_in[2];
    const int*   sid      = (const int*)d_in[3];
    const float* w_ih0 = (const float*)d_in[4];
    const float* w_hh0 = (const float*)d_in[5];
    const float* b_ih0 = (const float*)d_in[6];
    const float* b_hh0 = (const float*)d_in[7];
    const float* w_ih1 = (const float*)d_in[8];
    const float* w_hh1 = (const float*)d_in[9];
    const float* b_ih1 = (const float*)d_in[10];
    const float* b_hh1 = (const float*)d_in[11];
    const float* intra_W  = (const float*)d_in[12];
    const float* a_src_i  = (const float*)d_in[13];
    const float* a_dst_i  = (const float*)d_in[14];
    const float* bias_i   = (const float*)d_in[15];
    const float* inter_W  = (const float*)d_in[16];
    const float* a_src_e  = (const float*)d_in[17];
    const float* a_dst_e  = (const float*)d_in[18];
    const float* bias_e   = (const float*)d_in[19];
    const float* fw       = (const float*)d_in[20];
    const float* fb       = (const float*)d_in[21];
    float* out = (float*)d_out;

    cudaFuncSetAttribute(gru_step_k, cudaFuncAttributeMaxDynamicSharedMemorySize, STEP_SMEM);

    float *gi, *h, *hlin, *acc, *es, *ed, *m, *den, *eedge, *pool, *shlin, *sacc;
    __nv_bfloat16 *xb, *o0b, *hbA, *hbB, *wb_ih0, *wb_hh0, *wb_ih1, *wb_hh1, *wb_a, *wb_e, *poolb;
    unsigned *mu, *pu;
    cudaGetSymbolAddress((void**)&gi, g_gi);
    cudaGetSymbolAddress((void**)&xb, g_xb);
    cudaGetSymbolAddress((void**)&o0b, g_o0b);
    cudaGetSymbolAddress((void**)&h, g_h);
    cudaGetSymbolAddress((void**)&hbA, g_hbA);
    cudaGetSymbolAddress((void**)&hbB, g_hbB);
    cudaGetSymbolAddress((void**)&hlin, g_hlin);
    cudaGetSymbolAddress((void**)&acc, g_acc);
    cudaGetSymbolAddress((void**)&wb_ih0, g_wb_ih0);
    cudaGetSymbolAddress((void**)&wb_hh0, g_wb_hh0);
    cudaGetSymbolAddress((void**)&wb_ih1, g_wb_ih1);
    cudaGetSymbolAddress((void**)&wb_hh1, g_wb_hh1);
    cudaGetSymbolAddress((void**)&wb_a, g_wb_intra);
    cudaGetSymbolAddress((void**)&wb_e, g_wb_inter);
    cudaGetSymbolAddress((void**)&es, g_es);
    cudaGetSymbolAddress((void**)&ed, g_ed);
    cudaGetSymbolAddress((void**)&m, g_m);
    cudaGetSymbolAddress((void**)&den, g_den);
    cudaGetSymbolAddress((void**)&mu, g_mu);
    cudaGetSymbolAddress((void**)&eedge, g_eedge);
    cudaGetSymbolAddress((void**)&pu, g_pu);
    cudaGetSymbolAddress((void**)&pool, g_pool);
    cudaGetSymbolAddress((void**)&poolb, g_poolb);
    cudaGetSymbolAddress((void**)&shlin, g_shlin);
    cudaGetSymbolAddress((void**)&sacc, g_sacc);

    const dim3 stepGrid(4, (NN + 127) / 128);

    // ---- GRU layer 0 ----
    convw_int_k<<<(G3 * INP + 255) / 256, 256>>>(w_ih0, wb_ih0, INP);
    convw_k<<<(NN * TT * INP + 255) / 256, 256>>>(x, xb, NN * TT, INP);
    launch_gemm(xb, wb_ih0, gi, NN * TT, G3, INP);     // gi gate-interleaved
    convw_int_k<<<(G3 * HH + 255) / 256, 256>>>(w_hh0, wb_hh0, HH);
    zerof_k<<<(NN * HH + 255) / 256, 256>>>(h, NN * HH);
    zerou_k<<<(NN * HH + 255) / 256, 256>>>((unsigned*)hbA, NN * HH);
    {
        __nv_bfloat16* cur = hbA;
        __nv_bfloat16* nxt = hbB;
        for (int t = 0; t < TT; t++) {
            gru_step_k<<<stepGrid, 256, STEP_SMEM>>>(cur, nxt, wb_hh0, gi,
                                                     b_ih0, b_hh0, h, o0b, t, NN);
            __nv_bfloat16* tmp = cur; cur = nxt; nxt = tmp;
        }
    }

    // ---- GRU layer 1 ----
    convw_int_k<<<(G3 * HH + 255) / 256, 256>>>(w_ih1, wb_ih1, HH);
    launch_gemm(o0b, wb_ih1, gi, NN * TT, G3, HH);
    convw_int_k<<<(G3 * HH + 255) / 256, 256>>>(w_hh1, wb_hh1, HH);
    zerof_k<<<(NN * HH + 255) / 256, 256>>>(h, NN * HH);
    zerou_k<<<(NN * HH + 255) / 256, 256>>>((unsigned*)hbA, NN * HH);
    __nv_bfloat16* hbFinal;
    {
        __nv_bfloat16* cur = hbA;
        __nv_bfloat16* nxt = hbB;
        for (int t = 0; t < TT; t++) {
            gru_step_k<<<stepGrid, 256, STEP_SMEM>>>(cur, nxt, wb_hh1, gi,
                                                     b_ih1, b_hh1, h, nullptr, t, NN);
            __nv_bfloat16* tmp = cur; cur = nxt; nxt = tmp;
        }
        hbFinal = cur;   // after even TT swaps, cur == hbA (holds final state)
    }
    // h == seq_emb (fp32), hbFinal == its bf16 split

    // ---- intra GAT ----
    convw_k<<<(HH * HH + 255) / 256, 256>>>(intra_W, wb_a, HH, HH);
    launch_gemm(hbFinal, wb_a, hlin, NN, HH, HH);
    gat_scores_k<<<(NN * 32 + 255) / 256, 256>>>(hlin, a_src_i, a_dst_i, es, ed, mu, NN);
    gat_edge_max_k<<<(EINTRA + 255) / 256, 256>>>(ei_intra, es, ed, eedge, mu, EINTRA);
    gat_node_init_k<<<NN, HH>>>(hlin, es, ed, mu, m, den, acc);
    gat_edge_agg_k<<<(EINTRA * 32 + 255) / 256, 256>>>(ei_intra, eedge, m, hlin, den, acc, EINTRA);
    gat_finalize_k<<<NN, HH>>>(acc, den, bias_i);
    // acc == intra_emb

    // ---- sector max pool ----
    zerou_k<<<(SS * HH + 255) / 256, 256>>>(pu, SS * HH);
    pool_max_k<<<(NN * HH + 255) / 256, 256>>>(acc, sid, pu);
    pool_conv_k<<<(SS * HH + 255) / 256, 256>>>(pu, pool, poolb);

    // ---- inter GAT (S=64) ----
    convw_k<<<(HH * HH + 255) / 256, 256>>>(inter_W, wb_e, HH, HH);
    launch_gemm(poolb, wb_e, shlin, SS, HH, HH);
    gat_scores_k<<<(SS * 32 + 255) / 256, 256>>>(shlin, a_src_e, a_dst_e, es, ed, mu, SS);
    gat_edge_max_k<<<(EINTER + 255) / 256, 256>>>(ei_inter, es, ed, eedge, mu, EINTER);
    gat_node_init_k<<<SS, HH>>>(shlin, es, ed, mu, m, den, sacc);
    gat_edge_agg_k<<<(EINTER * 32 + 255) / 256, 256>>>(ei_inter, eedge, m, shlin, den, sacc, EINTER);
    gat_finalize_k<<<SS, HH>>>(sacc, den, bias_e);
    // sacc == inter_sec

    // ---- fusion ----
    fusion_k<<<(NN * 32 + 255) / 256, 256>>>(h, acc, sacc, sid, fw, fb, out);
}

// round 8
// speedup vs baseline: 1.3893x; 1.3729x over previous
#include <cuda_runtime.h>
#include <cuda_bf16.h>
#include <math.h>
#include <stdint.h>

#define NN     20000
#define TT     32
#define INP    64
#define HH     128
#define G3     384
#define SS     64
#define EINTRA 640000
#define EINTER 4096

// ---------------- scratch (static device globals; no allocs) ----------------
__device__ __align__(128) float g_gi[(size_t)NN*TT*G3];            // layer0 gi, 983 MB
__device__ __align__(128) __nv_bfloat16 g_xb[(size_t)NN*TT*2*INP]; // x as hi|lo
__device__ __align__(128) __nv_bfloat16 g_o0b[(size_t)NN*TT*2*HH]; // layer0 outputs hi|lo
__device__ __align__(128) float g_gh0[(size_t)NN*G3];
__device__ __align__(128) float g_gh1[(size_t)NN*G3];
__device__ __align__(128) float g_gi1[(size_t)NN*G3];
__device__ __align__(128) float g_h0[(size_t)NN*HH];
__device__ __align__(128) float g_h1[(size_t)NN*HH];
__device__ __align__(128) __nv_bfloat16 g_hb0[(size_t)NN*2*HH];
__device__ __align__(128) __nv_bfloat16 g_hb1[(size_t)NN*2*HH];
__device__ __align__(128) float g_hlin[(size_t)NN*HH];
__device__ __align__(128) float g_acc[(size_t)NN*HH];
__device__ __align__(128) __nv_bfloat16 g_wb_ih0[G3*2*INP];
__device__ __align__(128) __nv_bfloat16 g_wb_hh0[G3*2*HH];
__device__ __align__(128) __nv_bfloat16 g_wb_ih1[G3*2*HH];
__device__ __align__(128) __nv_bfloat16 g_wb_hh1[G3*2*HH];
__device__ __align__(128) __nv_bfloat16 g_wb_intra[HH*2*HH];
__device__ __align__(128) __nv_bfloat16 g_wb_inter[HH*2*HH];
__device__ float    g_es[NN];
__device__ float    g_ed[NN];
__device__ float    g_m[NN];
__device__ float    g_den[NN];
__device__ unsigned g_mu[NN];
__device__ float    g_eedge[EINTRA];
__device__ unsigned g_pu[SS*HH];
__device__ __align__(128) float g_pool[SS*HH];
__device__ __align__(128) __nv_bfloat16 g_poolb[SS*2*HH];
__device__ __align__(128) float g_shlin[SS*HH];
__device__ __align__(128) float g_sacc[SS*HH];

// ---------------- helpers ----------------
__device__ __forceinline__ uint32_t smem_u32(const void* p) {
    uint32_t a;
    asm("{ .reg .u64 t; cvta.to.shared.u64 t, %1; cvt.u32.u64 %0, t; }" : "=r"(a) : "l"(p));
    return a;
}
__device__ __forceinline__ unsigned fkey(float f) {
    unsigned u = __float_as_uint(f);
    return (u & 0x80000000u) ? ~u : (u | 0x80000000u);
}
__device__ __forceinline__ float funkey(unsigned k) {
    return (k & 0x80000000u) ? __uint_as_float(k & 0x7fffffffu)
                             : __uint_as_float(~k);
}
__device__ __forceinline__ float lrelu(float x) { return x > 0.f ? x : 0.2f * x; }

__device__ __forceinline__ void cp_async16(uint32_t saddr, const void* gaddr, int srcBytes) {
    asm volatile("cp.async.cg.shared.global [%0], [%1], 16, %2;"
                 :: "r"(saddr), "l"(gaddr), "r"(srcBytes) : "memory");
}
__device__ __forceinline__ void cp_commit() {
    asm volatile("cp.async.commit_group;" ::: "memory");
}
template <int N>
__device__ __forceinline__ void cp_wait() {
    asm volatile("cp.async.wait_group %0;" :: "n"(N) : "memory");
}
__device__ __forceinline__ void ldmatrix_x4(uint32_t* r, uint32_t addr) {
    asm volatile("ldmatrix.sync.aligned.m8n8.x4.shared.b16 {%0,%1,%2,%3}, [%4];"
                 : "=r"(r[0]), "=r"(r[1]), "=r"(r[2]), "=r"(r[3]) : "r"(addr));
}
__device__ __forceinline__ void mma16816(float* d, const uint32_t* a, uint32_t b0, uint32_t b1) {
    asm volatile(
        "mma.sync.aligned.m16n8k16.row.col.f32.bf16.bf16.f32 "
        "{%0,%1,%2,%3}, {%4,%5,%6,%7}, {%8,%9}, {%0,%1,%2,%3};"
        : "+f"(d[0]), "+f"(d[1]), "+f"(d[2]), "+f"(d[3])
        : "r"(a[0]), "r"(a[1]), "r"(a[2]), "r"(a[3]), "r"(b0), "r"(b1));
}

// ---------------- misc kernels ----------------
__global__ void zerof_k(float* p, int n) {
    int i = blockIdx.x * blockDim.x + threadIdx.x;
    if (i < n) p[i] = 0.f;
}
__global__ void zerou_k(unsigned* p, int n) {
    int i = blockIdx.x * blockDim.x + threadIdx.x;
    if (i < n) p[i] = 0u;
}
// split fp32 [rows,K] -> bf16 [rows, 2K] as [hi | lo]
__global__ void convw_k(const float* __restrict__ W, __nv_bfloat16* __restrict__ Wb,
                        int rows, int K) {
    int idx = blockIdx.x * blockDim.x + threadIdx.x;
    if (idx >= rows * K) return;
    int r = idx / K, c = idx % K;
    float v = W[idx];
    __nv_bfloat16 hi = __float2bfloat16(v);
    __nv_bfloat16 lo = __float2bfloat16(v - __bfloat162float(hi));
    Wb[(size_t)r * 2 * K + c]     = hi;
    Wb[(size_t)r * 2 * K + K + c] = lo;
}

// ---------------- tensor-core GEMM body (mma.sync bf16): C = split(A) @ split(B)^T
// Ab rows at stride ldA elems, each row [hi(K) | lo(K)]; Bb [Nc, 2K]; C [M,Nc] fp32.
// Computes Ahi@Bhi^T + Alo@Bhi^T + Ahi@Blo^T. Tile 128x128xBK32, cp.async
// double buffer, XOR-swizzled smem, 8 warps each 32x64.
__device__ __forceinline__ void gemm_body(
    char* smbuf,
    const __nv_bfloat16* __restrict__ Ab, int ldA,
    const __nv_bfloat16* __restrict__ Bb,
    float* __restrict__ C, int M, int Nc, int K, int bm, int bn)
{
    const uint32_t sb = smem_u32(smbuf);
    const int tid = threadIdx.x;
    const int wid = tid >> 5, lane = tid & 31;
    const int wm = wid & 3;
    const int wn = wid >> 2;
    const int ldB = 2 * K;

    const int cpk = K >> 5;
    const int nk = 3 * cpk;

    float d[2][8][4];
#pragma unroll
    for (int i = 0; i < 2; i++)
#pragma unroll
        for (int j = 0; j < 8; j++)
#pragma unroll
            for (int q = 0; q < 4; q++) d[i][j][q] = 0.f;

    auto issue_loads = [&](int kb, int s) {
        const int seg = kb / cpk, kc = kb - seg * cpk;
        const int acol = (seg == 1 ? K : 0) + (kc << 5);
        const int bcol = (seg == 2 ? K : 0) + (kc << 5);
        const __nv_bfloat16* Abase = Ab + acol;
        const __nv_bfloat16* Bbase = Bb + bcol;
        const uint32_t sA = sb + s * 16384;
        const uint32_t sB = sA + 8192;
#pragma unroll
        for (int i = 0; i < 2; i++) {
            int cid = tid + (i << 8);
            int r = cid >> 2, c = cid & 3;
            uint32_t soff = (uint32_t)(r << 6) + (uint32_t)((c ^ ((r >> 1) & 3)) << 4);
            int arow = bm + r;
            const char* ga = (const char*)(Abase + (size_t)(arow < M ? arow : 0) * ldA) + (c << 4);
            cp_async16(sA + soff, ga, arow < M ? 16 : 0);
            const char* gb = (const char*)(Bbase + (size_t)(bn + r) * ldB) + (c << 4);
            cp_async16(sB + soff, gb, 16);
        }
        cp_commit();
    };

    issue_loads(0, 0);

    for (int kb = 0; kb < nk; kb++) {
        const int s = kb & 1;
        if (kb + 1 < nk) issue_loads(kb + 1, s ^ 1);
        if (kb + 1 < nk) cp_wait<1>(); else cp_wait<0>();
        __syncthreads();

        const uint32_t sA = sb + s * 16384;
        const uint32_t sB = sA + 8192;
        const int lr = lane & 15;
        const int lk = (lane >> 4) << 4;
#pragma unroll
        for (int k16 = 0; k16 < 2; k16++) {
            const int kby = (k16 << 5) + lk;
            const int csel = kby >> 4;
            uint32_t a[2][4], bf[4][4];
#pragma unroll
            for (int mt = 0; mt < 2; mt++) {
                int r = wm * 32 + mt * 16 + lr;
                uint32_t addr = sA + (uint32_t)(r << 6) + (uint32_t)((csel ^ ((r >> 1) & 3)) << 4);
                ldmatrix_x4(a[mt], addr);
            }
#pragma unroll
            for (int p = 0; p < 4; p++) {
                int r = wn * 64 + p * 16 + lr;
                uint32_t addr = sB + (uint32_t)(r << 6) + (uint32_t)((csel ^ ((r >> 1) & 3)) << 4);
                ldmatrix_x4(bf[p], addr);
            }
#pragma unroll
            for (int mt = 0; mt < 2; mt++)
#pragma unroll
                for (int nt = 0; nt < 8; nt++) {
                    int p = nt >> 1, hi = nt & 1;
                    mma16816(d[mt][nt], a[mt], bf[p][hi], bf[p][2 + hi]);
                }
        }
        __syncthreads();
    }

    const int gr = lane >> 2;
    const int gc = (lane & 3) << 1;
#pragma unroll
    for (int mt = 0; mt < 2; mt++) {
        int r0 = bm + wm * 32 + mt * 16 + gr;
#pragma unroll
        for (int nt = 0; nt < 8; nt++) {
            int cc = bn + wn * 64 + nt * 8 + gc;
            if (r0 < M)
                *(float2*)(C + (size_t)r0 * Nc + cc) = make_float2(d[mt][nt][0], d[mt][nt][1]);
            if (r0 + 8 < M)
                *(float2*)(C + (size_t)(r0 + 8) * Nc + cc) = make_float2(d[mt][nt][2], d[mt][nt][3]);
        }
    }
}

// single-problem GEMM kernel
__global__ void __launch_bounds__(256) gemm_mma_k(
    const __nv_bfloat16* __restrict__ Ab, int ldA,
    const __nv_bfloat16* __restrict__ Bb,
    float* __restrict__ C, int M, int Nc, int K)
{
    __shared__ __align__(16) char smbuf[32768];
    gemm_body(smbuf, Ab, ldA, Bb, C, M, Nc, K, blockIdx.y * 128, blockIdx.x * 128);
}

// 3-problem GEMM (pipelined recurrent step): z=0 gh0, z=1 gi1, z=2 gh1.
// All are [NN,384] = A[NN, hi|lo 256] @ B[384,256]^T with K=128.
__global__ void __launch_bounds__(256) gemm3_k(
    const __nv_bfloat16* __restrict__ A0,
    const __nv_bfloat16* __restrict__ A1, int ld1,
    const __nv_bfloat16* __restrict__ A2,
    const __nv_bfloat16* __restrict__ B0,
    const __nv_bfloat16* __restrict__ B1,
    const __nv_bfloat16* __restrict__ B2,
    float* __restrict__ C0, float* __restrict__ C1, float* __restrict__ C2,
    int act0, int act1)
{
    __shared__ __align__(16) char smbuf[32768];
    const int bm = blockIdx.y * 128, bn = blockIdx.x * 128;
    if (blockIdx.z == 0) {
        if (!act0) return;
        gemm_body(smbuf, A0, 2 * HH, B0, C0, NN, G3, HH, bm, bn);
    } else if (blockIdx.z == 1) {
        if (!act1) return;
        gemm_body(smbuf, A1, ld1, B1, C1, NN, G3, HH, bm, bn);
    } else {
        if (!act1) return;
        gemm_body(smbuf, A2, 2 * HH, B2, C2, NN, G3, HH, bm, bn);
    }
}

// ---------------- dual-layer GRU pointwise cell ----------------
// y=0: layer0 (gi from big array slice t0, writes h0/hb0/o0b[t0])
// y=1: layer1 (gi1 linear [i*G3+j], writes h1/hb1)
__global__ void cell2_k(const float* __restrict__ gi0, const float* __restrict__ gh0,
                        const float* __restrict__ bih0, const float* __restrict__ bhh0,
                        float* __restrict__ h0, __nv_bfloat16* __restrict__ hb0,
                        __nv_bfloat16* __restrict__ o0b,
                        const float* __restrict__ gi1, const float* __restrict__ gh1,
                        const float* __restrict__ bih1, const float* __restrict__ bhh1,
                        float* __restrict__ h1, __nv_bfloat16* __restrict__ hb1,
                        int t0, int act0, int act1) {
    int idx = blockIdx.x * blockDim.x + threadIdx.x;
    if (idx >= NN * HH) return;
    int i = idx >> 7;
    int j = idx & 127;
    if (blockIdx.y == 0) {
        if (!act0) return;
        size_t mg = ((size_t)i * TT + t0) * G3;
        size_t hg = (size_t)i * G3;
        float ir  = gi0[mg + j]          + bih0[j];
        float iz  = gi0[mg + HH + j]     + bih0[HH + j];
        float inn = gi0[mg + 2 * HH + j] + bih0[2 * HH + j];
        float hr  = gh0[hg + j]          + bhh0[j];
        float hz  = gh0[hg + HH + j]     + bhh0[HH + j];
        float hn  = gh0[hg + 2 * HH + j] + bhh0[2 * HH + j];
        float r = 1.f / (1.f + expf(-(ir + hr)));
        float z = 1.f / (1.f + expf(-(iz + hz)));
        float n = tanhf(inn + r * hn);
        float hold = h0[idx];
        float hnew = (1.f - z) * n + z * hold;
        h0[idx] = hnew;
        __nv_bfloat16 hi = __float2bfloat16(hnew);
        __nv_bfloat16 lo = __float2bfloat16(hnew - __bfloat162float(hi));
        hb0[(size_t)i * 256 + j]      = hi;
        hb0[(size_t)i * 256 + HH + j] = lo;
        size_t ro = ((size_t)i * TT + t0) * 256;
        o0b[ro + j]      = hi;
        o0b[ro + HH + j] = lo;
    } else {
        if (!act1) return;
        size_t hg = (size_t)i * G3;
        float ir  = gi1[hg + j]          + bih1[j];
        float iz  = gi1[hg + HH + j]     + bih1[HH + j];
        float inn = gi1[hg + 2 * HH + j] + bih1[2 * HH + j];
        float hr  = gh1[hg + j]          + bhh1[j];
        float hz  = gh1[hg + HH + j]     + bhh1[HH + j];
        float hn  = gh1[hg + 2 * HH + j] + bhh1[2 * HH + j];
        float r = 1.f / (1.f + expf(-(ir + hr)));
        float z = 1.f / (1.f + expf(-(iz + hz)));
        float n = tanhf(inn + r * hn);
        float hold = h1[idx];
        float hnew = (1.f - z) * n + z * hold;
        h1[idx] = hnew;
        __nv_bfloat16 hi = __float2bfloat16(hnew);
        __nv_bfloat16 lo = __float2bfloat16(hnew - __bfloat162float(hi));
        hb1[(size_t)i * 256 + j]      = hi;
        hb1[(size_t)i * 256 + HH + j] = lo;
    }
}

// ---------------- GAT kernels ----------------
__global__ void gat_scores_k(const float* __restrict__ hlin,
                             const float* __restrict__ asrc, const float* __restrict__ adst,
                             float* __restrict__ es, float* __restrict__ ed,
                             unsigned* __restrict__ mu, int n) {
    int g = blockIdx.x * blockDim.x + threadIdx.x;
    int node = g >> 5;
    int lane = g & 31;
    if (node >= n) return;
    float4 h4 = reinterpret_cast<const float4*>(hlin + (size_t)node * HH)[lane];
    float4 a4 = reinterpret_cast<const float4*>(asrc)[lane];
    float4 d4 = reinterpret_cast<const float4*>(adst)[lane];
    float s = h4.x * a4.x + h4.y * a4.y + h4.z * a4.z + h4.w * a4.w;
    float d = h4.x * d4.x + h4.y * d4.y + h4.z * d4.z + h4.w * d4.w;
#pragma unroll
    for (int o = 16; o; o >>= 1) {
        s += __shfl_xor_sync(0xffffffffu, s, o);
        d += __shfl_xor_sync(0xffffffffu, d, o);
    }
    if (lane == 0) {
        es[node] = s;
        ed[node] = d;
        mu[node] = fkey(lrelu(s + d));
    }
}

__global__ void gat_edge_max_k(const int* __restrict__ ei,
                               const float* __restrict__ es, const float* __restrict__ ed,
                               float* __restrict__ eedge, unsigned* __restrict__ mu, int E) {
    int e = blockIdx.x * blockDim.x + threadIdx.x;
    if (e >= E) return;
    int s = ei[e];
    int d = ei[E + e];
    float v = lrelu(es[s] + ed[d]);
    eedge[e] = v;
    atomicMax(&mu[d], fkey(v));
}

__global__ void gat_node_init_k(const float* __restrict__ hlin,
                                const float* __restrict__ es, const float* __restrict__ ed,
                                const unsigned* __restrict__ mu,
                                float* __restrict__ m, float* __restrict__ den,
                                float* __restrict__ acc) {
    int i = blockIdx.x;
    int j = threadIdx.x;
    float mv = funkey(mu[i]);
    float w0 = expf(lrelu(es[i] + ed[i]) - mv);
    if (j == 0) { m[i] = mv; den[i] = w0; }
    acc[(size_t)i * HH + j] = w0 * hlin[(size_t)i * HH + j];
}

__global__ void gat_edge_agg_k(const int* __restrict__ ei, const float* __restrict__ eedge,
                               const float* __restrict__ m, const float* __restrict__ hlin,
                               float* __restrict__ den, float* __restrict__ acc, int E) {
    int g = blockIdx.x * blockDim.x + threadIdx.x;
    int e = g >> 5;
    int lane = g & 31;
    if (e >= E) return;
    int s = ei[e];
    int d = ei[E + e];
    float w = expf(eedge[e] - m[d]);
    if (lane == 0) atomicAdd(&den[d], w);
    float4 hv = reinterpret_cast<const float4*>(hlin + (size_t)s * HH)[lane];
    float* ap = acc + (size_t)d * HH + 4 * lane;
    atomicAdd(ap + 0, w * hv.x);
    atomicAdd(ap + 1, w * hv.y);
    atomicAdd(ap + 2, w * hv.z);
    atomicAdd(ap + 3, w * hv.w);
}

__global__ void gat_finalize_k(float* __restrict__ acc, const float* __restrict__ den,
                               const float* __restrict__ bias) {
    int i = blockIdx.x;
    int j = threadIdx.x;
    acc[(size_t)i * HH + j] = acc[(size_t)i * HH + j] / den[i] + bias[j];
}

// ---------------- sector max pool ----------------
__global__ void pool_max_k(const float* __restrict__ x, const int* __restrict__ sid,
                           unsigned* __restrict__ pu) {
    int idx = blockIdx.x * blockDim.x + threadIdx.x;
    if (idx >= NN * HH) return;
    int i = idx >> 7;
    int j = idx & 127;
    atomicMax(&pu[sid[i] * HH + j], fkey(x[idx]));
}
__global__ void pool_conv_k(const unsigned* __restrict__ pu, float* __restrict__ p,
                            __nv_bfloat16* __restrict__ pb) {
    int idx = blockIdx.x * blockDim.x + threadIdx.x;
    if (idx >= SS * HH) return;
    int r = idx >> 7, j = idx & 127;
    float v = funkey(pu[idx]);
    p[idx] = v;
    __nv_bfloat16 hi = __float2bfloat16(v);
    __nv_bfloat16 lo = __float2bfloat16(v - __bfloat162float(hi));
    pb[(size_t)r * 2 * HH + j]      = hi;
    pb[(size_t)r * 2 * HH + HH + j] = lo;
}

// ---------------- fusion head ----------------
__global__ void fusion_k(const float* __restrict__ seq, const float* __restrict__ intra,
                         const float* __restrict__ inter, const int* __restrict__ sid,
                         const float* __restrict__ fw, const float* __restrict__ fb,
                         float* __restrict__ out) {
    int g = blockIdx.x * blockDim.x + threadIdx.x;
    int i = g >> 5;
    int lane = g & 31;
    if (i >= NN) return;
    int sc = sid[i];
    const float4* s4 = reinterpret_cast<const float4*>(seq + (size_t)i * HH);
    const float4* i4 = reinterpret_cast<const float4*>(intra + (size_t)i * HH);
    const float4* e4 = reinterpret_cast<const float4*>(inter + (size_t)sc * HH);
    const float4* w4 = reinterpret_cast<const float4*>(fw);
    float sum = 0.f;
    float4 a, b;
    a = s4[lane]; b = w4[lane];
    sum += a.x * b.x + a.y * b.y + a.z * b.z + a.w * b.w;
    a = i4[lane]; b = w4[32 + lane];
    sum += a.x * b.x + a.y * b.y + a.z * b.z + a.w * b.w;
    a = e4[lane]; b = w4[64 + lane];
    sum += a.x * b.x + a.y * b.y + a.z * b.z + a.w * b.w;
#pragma unroll
    for (int o = 16; o; o >>= 1) sum += __shfl_xor_sync(0xffffffffu, sum, o);
    if (lane == 0) out[i] = sum + fb[0];
}

// ---------------- host ----------------
static inline void launch_gemm(const __nv_bfloat16* Ab, const __nv_bfloat16* Bb,
                               float* C, int M, int Nc, int K) {
    dim3 grid(Nc / 128, (M + 127) / 128);
    gemm_mma_k<<<grid, 256>>>(Ab, 2 * K, Bb, C, M, Nc, K);
}

extern "C" void kernel_launch(void* const* d_in, const int* in_sizes, int n_in,
                              void* d_out, int out_size) {
    const float* x        = (const float*)d_in[0];
    const int*   ei_intra = (const int*)d_in[1];
    const int*   ei_inter = (const int*)d_in[2];
    const int*   sid      = (const int*)d_in[3];
    const float* w_ih0 = (const float*)d_in[4];
    const float* w_hh0 = (const float*)d_in[5];
    const float* b_ih0 = (const float*)d_in[6];
    const float* b_hh0 = (const float*)d_in[7];
    const float* w_ih1 = (const float*)d_in[8];
    const float* w_hh1 = (const float*)d_in[9];
    const float* b_ih1 = (const float*)d_in[10];
    const float* b_hh1 = (const float*)d_in[11];
    const float* intra_W  = (const float*)d_in[12];
    const float* a_src_i  = (const float*)d_in[13];
    const float* a_dst_i  = (const float*)d_in[14];
    const float* bias_i   = (const float*)d_in[15];
    const float* inter_W  = (const float*)d_in[16];
    const float* a_src_e  = (const float*)d_in[17];
    const float* a_dst_e  = (const float*)d_in[18];
    const float* bias_e   = (const float*)d_in[19];
    const float* fw       = (const float*)d_in[20];
    const float* fb       = (const float*)d_in[21];
    float* out = (float*)d_out;

    float *gi, *gh0, *gh1, *gi1, *h0, *h1, *hlin, *acc;
    float *es, *ed, *m, *den, *eedge, *pool, *shlin, *sacc;
    __nv_bfloat16 *xb, *o0b, *hb0, *hb1, *wb_ih0, *wb_hh0, *wb_ih1, *wb_hh1, *wb_a, *wb_e, *poolb;
    unsigned *mu, *pu;
    cudaGetSymbolAddress((void**)&gi, g_gi);
    cudaGetSymbolAddress((void**)&xb, g_xb);
    cudaGetSymbolAddress((void**)&o0b, g_o0b);
    cudaGetSymbolAddress((void**)&gh0, g_gh0);
    cudaGetSymbolAddress((void**)&gh1, g_gh1);
    cudaGetSymbolAddress((void**)&gi1, g_gi1);
    cudaGetSymbolAddress((void**)&h0, g_h0);
    cudaGetSymbolAddress((void**)&h1, g_h1);
    cudaGetSymbolAddress((void**)&hb0, g_hb0);
    cudaGetSymbolAddress((void**)&hb1, g_hb1);
    cudaGetSymbolAddress((void**)&hlin, g_hlin);
    cudaGetSymbolAddress((void**)&acc, g_acc);
    cudaGetSymbolAddress((void**)&wb_ih0, g_wb_ih0);
    cudaGetSymbolAddress((void**)&wb_hh0, g_wb_hh0);
    cudaGetSymbolAddress((void**)&wb_ih1, g_wb_ih1);
    cudaGetSymbolAddress((void**)&wb_hh1, g_wb_hh1);
    cudaGetSymbolAddress((void**)&wb_a, g_wb_intra);
    cudaGetSymbolAddress((void**)&wb_e, g_wb_inter);
    cudaGetSymbolAddress((void**)&es, g_es);
    cudaGetSymbolAddress((void**)&ed, g_ed);
    cudaGetSymbolAddress((void**)&m, g_m);
    cudaGetSymbolAddress((void**)&den, g_den);
    cudaGetSymbolAddress((void**)&mu, g_mu);
    cudaGetSymbolAddress((void**)&eedge, g_eedge);
    cudaGetSymbolAddress((void**)&pu, g_pu);
    cudaGetSymbolAddress((void**)&pool, g_pool);
    cudaGetSymbolAddress((void**)&poolb, g_poolb);
    cudaGetSymbolAddress((void**)&shlin, g_shlin);
    cudaGetSymbolAddress((void**)&sacc, g_sacc);

    const int cellGrid = (NN * HH + 255) / 256;

    // ---- prep: weight splits, input split, layer-0 input GEMM ----
    convw_k<<<(G3 * INP + 255) / 256, 256>>>(w_ih0, wb_ih0, G3, INP);
    convw_k<<<(NN * TT * INP + 255) / 256, 256>>>(x, xb, NN * TT, INP);
    launch_gemm(xb, wb_ih0, gi, NN * TT, G3, INP);
    convw_k<<<(G3 * HH + 255) / 256, 256>>>(w_hh0, wb_hh0, G3, HH);
    convw_k<<<(G3 * HH + 255) / 256, 256>>>(w_ih1, wb_ih1, G3, HH);
    convw_k<<<(G3 * HH + 255) / 256, 256>>>(w_hh1, wb_hh1, G3, HH);
    zerof_k<<<(NN * HH + 255) / 256, 256>>>(h0, NN * HH);
    zerof_k<<<(NN * HH + 255) / 256, 256>>>(h1, NN * HH);
    zerou_k<<<(NN * HH + 255) / 256, 256>>>((unsigned*)hb0, NN * HH);
    zerou_k<<<(NN * HH + 255) / 256, 256>>>((unsigned*)hb1, NN * HH);

    // ---- pipelined GRU: iteration it runs layer0 step it & layer1 step it-1 ----
    const dim3 g3grid(3, (NN + 127) / 128, 3);
    const dim3 cellG(cellGrid, 2);
    for (int it = 0; it <= TT; it++) {
        const int act0 = (it < TT) ? 1 : 0;
        const int act1 = (it >= 1) ? 1 : 0;
        const int t0 = it, t1 = it - 1;
        gemm3_k<<<g3grid, 256>>>(hb0,
                                 o0b + (size_t)(act1 ? t1 : 0) * 256, TT * 256,
                                 hb1,
                                 wb_hh0, wb_ih1, wb_hh1,
                                 gh0, gi1, gh1, act0, act1);
        cell2_k<<<cellG, 256>>>(gi, gh0, b_ih0, b_hh0, h0, hb0, o0b,
                                gi1, gh1, b_ih1, b_hh1, h1, hb1,
                                t0, act0, act1);
    }
    // h1 == seq_emb (fp32), hb1 == its bf16 split

    // ---- intra GAT ----
    convw_k<<<(HH * HH + 255) / 256, 256>>>(intra_W, wb_a, HH, HH);
    launch_gemm(hb1, wb_a, hlin, NN, HH, HH);
    gat_scores_k<<<(NN * 32 + 255) / 256, 256>>>(hlin, a_src_i, a_dst_i, es, ed, mu, NN);
    gat_edge_max_k<<<(EINTRA + 255) / 256, 256>>>(ei_intra, es, ed, eedge, mu, EINTRA);
    gat_node_init_k<<<NN, HH>>>(hlin, es, ed, mu, m, den, acc);
    gat_edge_agg_k<<<(EINTRA * 32 + 255) / 256, 256>>>(ei_intra, eedge, m, hlin, den, acc, EINTRA);
    gat_finalize_k<<<NN, HH>>>(acc, den, bias_i);
    // acc == intra_emb

    // ---- sector max pool ----
    zerou_k<<<(SS * HH + 255) / 256, 256>>>(pu, SS * HH);
    pool_max_k<<<(NN * HH + 255) / 256, 256>>>(acc, sid, pu);
    pool_conv_k<<<(SS * HH + 255) / 256, 256>>>(pu, pool, poolb);

    // ---- inter GAT (S=64) ----
    convw_k<<<(HH * HH + 255) / 256, 256>>>(inter_W, wb_e, HH, HH);
    launch_gemm(poolb, wb_e, shlin, SS, HH, HH);
    gat_scores_k<<<(SS * 32 + 255) / 256, 256>>>(shlin, a_src_e, a_dst_e, es, ed, mu, SS);
    gat_edge_max_k<<<(EINTER + 255) / 256, 256>>>(ei_inter, es, ed, eedge, mu, EINTER);
    gat_node_init_k<<<SS, HH>>>(shlin, es, ed, mu, m, den, sacc);
    gat_edge_agg_k<<<(EINTER * 32 + 255) / 256, 256>>>(ei_inter, eedge, m, shlin, den, sacc, EINTER);
    gat_finalize_k<<<SS, HH>>>(sacc, den, bias_e);
    // sacc == inter_sec

    // ---- fusion ----
    fusion_k<<<(NN * 32 + 255) / 256, 256>>>(h1, acc, sacc, sid, fw, fb, out);
}

// round 9
// speedup vs baseline: 1.5510x; 1.1164x over previous
#include <cuda_runtime.h>
#include <cuda_bf16.h>
#include <math.h>
#include <stdint.h>

#define NN     20000
#define TT     32
#define INP    64
#define HH     128
#define G3     384
#define SS     64
#define EINTRA 640000
#define EINTER 4096

// ---------------- scratch (static device globals; no allocs) ----------------
__device__ __align__(128) float g_gi[(size_t)NN*TT*G3];            // layer0 gi, 983 MB
__device__ __align__(128) __nv_bfloat16 g_xb[(size_t)NN*TT*2*INP]; // x as hi|lo
__device__ __align__(128) float g_g01[(size_t)NN*768];             // [gh0 | gi1] fused
__device__ __align__(128) float g_gh1[(size_t)NN*G3];
__device__ __align__(128) float g_h0[(size_t)NN*HH];
__device__ __align__(128) float g_h1[(size_t)NN*HH];
__device__ __align__(128) __nv_bfloat16 g_hb0[(size_t)NN*2*HH];
__device__ __align__(128) __nv_bfloat16 g_hb1[(size_t)NN*2*HH];
__device__ __align__(128) float g_hlin[(size_t)NN*HH];
__device__ __align__(128) float g_acc[(size_t)NN*HH];
__device__ __align__(128) __nv_bfloat16 g_wb_ih0[G3*2*INP];
__device__ __align__(128) __nv_bfloat16 g_wb_s0[2*G3*2*HH];        // [Whh0 ; Wih1] stacked, 768x256
__device__ __align__(128) __nv_bfloat16 g_wb_hh1[G3*2*HH];
__device__ __align__(128) __nv_bfloat16 g_wb_intra[HH*2*HH];
__device__ __align__(128) __nv_bfloat16 g_wb_inter[HH*2*HH];
__device__ float    g_es[NN];
__device__ float    g_ed[NN];
__device__ float    g_m[NN];
__device__ float    g_den[NN];
__device__ unsigned g_mu[NN];
__device__ float    g_eedge[EINTRA];
__device__ unsigned g_pu[SS*HH];
__device__ __align__(128) float g_pool[SS*HH];
__device__ __align__(128) __nv_bfloat16 g_poolb[SS*2*HH];
__device__ __align__(128) float g_shlin[SS*HH];
__device__ __align__(128) float g_sacc[SS*HH];

// ---------------- helpers ----------------
__device__ __forceinline__ uint32_t smem_u32(const void* p) {
    uint32_t a;
    asm("{ .reg .u64 t; cvta.to.shared.u64 t, %1; cvt.u32.u64 %0, t; }" : "=r"(a) : "l"(p));
    return a;
}
__device__ __forceinline__ unsigned fkey(float f) {
    unsigned u = __float_as_uint(f);
    return (u & 0x80000000u) ? ~u : (u | 0x80000000u);
}
__device__ __forceinline__ float funkey(unsigned k) {
    return (k & 0x80000000u) ? __uint_as_float(k & 0x7fffffffu)
                             : __uint_as_float(~k);
}
__device__ __forceinline__ float lrelu(float x) { return x > 0.f ? x : 0.2f * x; }

__device__ __forceinline__ void cp_async16(uint32_t saddr, const void* gaddr, int srcBytes) {
    asm volatile("cp.async.cg.shared.global [%0], [%1], 16, %2;"
                 :: "r"(saddr), "l"(gaddr), "r"(srcBytes) : "memory");
}
__device__ __forceinline__ void cp_commit() {
    asm volatile("cp.async.commit_group;" ::: "memory");
}
template <int N>
__device__ __forceinline__ void cp_wait() {
    asm volatile("cp.async.wait_group %0;" :: "n"(N) : "memory");
}
__device__ __forceinline__ void ldmatrix_x4(uint32_t* r, uint32_t addr) {
    asm volatile("ldmatrix.sync.aligned.m8n8.x4.shared.b16 {%0,%1,%2,%3}, [%4];"
                 : "=r"(r[0]), "=r"(r[1]), "=r"(r[2]), "=r"(r[3]) : "r"(addr));
}
__device__ __forceinline__ void mma16816(float* d, const uint32_t* a, uint32_t b0, uint32_t b1) {
    asm volatile(
        "mma.sync.aligned.m16n8k16.row.col.f32.bf16.bf16.f32 "
        "{%0,%1,%2,%3}, {%4,%5,%6,%7}, {%8,%9}, {%0,%1,%2,%3};"
        : "+f"(d[0]), "+f"(d[1]), "+f"(d[2]), "+f"(d[3])
        : "r"(a[0]), "r"(a[1]), "r"(a[2]), "r"(a[3]), "r"(b0), "r"(b1));
}
// vector global reduction (sm_90+): one op per 16B
__device__ __forceinline__ void red_add_v4(float* p, float a, float b, float c, float d) {
    asm volatile("red.global.add.v4.f32 [%0], {%1, %2, %3, %4};"
                 :: "l"(p), "f"(a), "f"(b), "f"(c), "f"(d) : "memory");
}

// ---------------- misc kernels ----------------
__global__ void zerof_k(float* p, int n) {
    int i = blockIdx.x * blockDim.x + threadIdx.x;
    if (i < n) p[i] = 0.f;
}
__global__ void zerou_k(unsigned* p, int n) {
    int i = blockIdx.x * blockDim.x + threadIdx.x;
    if (i < n) p[i] = 0u;
}
// split fp32 [rows,K] -> bf16 [rows, 2K] as [hi | lo]
__global__ void convw_k(const float* __restrict__ W, __nv_bfloat16* __restrict__ Wb,
                        int rows, int K) {
    int idx = blockIdx.x * blockDim.x + threadIdx.x;
    if (idx >= rows * K) return;
    int r = idx / K, c = idx % K;
    float v = W[idx];
    __nv_bfloat16 hi = __float2bfloat16(v);
    __nv_bfloat16 lo = __float2bfloat16(v - __bfloat162float(hi));
    Wb[(size_t)r * 2 * K + c]     = hi;
    Wb[(size_t)r * 2 * K + K + c] = lo;
}

// ---------------- tensor-core GEMM body (mma.sync bf16): C = split(A) @ split(B)^T
__device__ __forceinline__ void gemm_body(
    char* smbuf,
    const __nv_bfloat16* __restrict__ Ab, int ldA,
    const __nv_bfloat16* __restrict__ Bb,
    float* __restrict__ C, int M, int Nc, int K, int bm, int bn)
{
    const uint32_t sb = smem_u32(smbuf);
    const int tid = threadIdx.x;
    const int wid = tid >> 5, lane = tid & 31;
    const int wm = wid & 3;
    const int wn = wid >> 2;
    const int ldB = 2 * K;

    const int cpk = K >> 5;
    const int nk = 3 * cpk;

    float d[2][8][4];
#pragma unroll
    for (int i = 0; i < 2; i++)
#pragma unroll
        for (int j = 0; j < 8; j++)
#pragma unroll
            for (int q = 0; q < 4; q++) d[i][j][q] = 0.f;

    auto issue_loads = [&](int kb, int s) {
        const int seg = kb / cpk, kc = kb - seg * cpk;
        const int acol = (seg == 1 ? K : 0) + (kc << 5);
        const int bcol = (seg == 2 ? K : 0) + (kc << 5);
        const __nv_bfloat16* Abase = Ab + acol;
        const __nv_bfloat16* Bbase = Bb + bcol;
        const uint32_t sA = sb + s * 16384;
        const uint32_t sB = sA + 8192;
#pragma unroll
        for (int i = 0; i < 2; i++) {
            int cid = tid + (i << 8);
            int r = cid >> 2, c = cid & 3;
            uint32_t soff = (uint32_t)(r << 6) + (uint32_t)((c ^ ((r >> 1) & 3)) << 4);
            int arow = bm + r;
            const char* ga = (const char*)(Abase + (size_t)(arow < M ? arow : 0) * ldA) + (c << 4);
            cp_async16(sA + soff, ga, arow < M ? 16 : 0);
            const char* gb = (const char*)(Bbase + (size_t)(bn + r) * ldB) + (c << 4);
            cp_async16(sB + soff, gb, 16);
        }
        cp_commit();
    };

    issue_loads(0, 0);

    for (int kb = 0; kb < nk; kb++) {
        const int s = kb & 1;
        if (kb + 1 < nk) issue_loads(kb + 1, s ^ 1);
        if (kb + 1 < nk) cp_wait<1>(); else cp_wait<0>();
        __syncthreads();

        const uint32_t sA = sb + s * 16384;
        const uint32_t sB = sA + 8192;
        const int lr = lane & 15;
        const int lk = (lane >> 4) << 4;
#pragma unroll
        for (int k16 = 0; k16 < 2; k16++) {
            const int kby = (k16 << 5) + lk;
            const int csel = kby >> 4;
            uint32_t a[2][4], bf[4][4];
#pragma unroll
            for (int mt = 0; mt < 2; mt++) {
                int r = wm * 32 + mt * 16 + lr;
                uint32_t addr = sA + (uint32_t)(r << 6) + (uint32_t)((csel ^ ((r >> 1) & 3)) << 4);
                ldmatrix_x4(a[mt], addr);
            }
#pragma unroll
            for (int p = 0; p < 4; p++) {
                int r = wn * 64 + p * 16 + lr;
                uint32_t addr = sB + (uint32_t)(r << 6) + (uint32_t)((csel ^ ((r >> 1) & 3)) << 4);
                ldmatrix_x4(bf[p], addr);
            }
#pragma unroll
            for (int mt = 0; mt < 2; mt++)
#pragma unroll
                for (int nt = 0; nt < 8; nt++) {
                    int p = nt >> 1, hi = nt & 1;
                    mma16816(d[mt][nt], a[mt], bf[p][hi], bf[p][2 + hi]);
                }
        }
        __syncthreads();
    }

    const int gr = lane >> 2;
    const int gc = (lane & 3) << 1;
#pragma unroll
    for (int mt = 0; mt < 2; mt++) {
        int r0 = bm + wm * 32 + mt * 16 + gr;
#pragma unroll
        for (int nt = 0; nt < 8; nt++) {
            int cc = bn + wn * 64 + nt * 8 + gc;
            if (r0 < M)
                *(float2*)(C + (size_t)r0 * Nc + cc) = make_float2(d[mt][nt][0], d[mt][nt][1]);
            if (r0 + 8 < M)
                *(float2*)(C + (size_t)(r0 + 8) * Nc + cc) = make_float2(d[mt][nt][2], d[mt][nt][3]);
        }
    }
}

// single-problem GEMM kernel
__global__ void __launch_bounds__(256) gemm_mma_k(
    const __nv_bfloat16* __restrict__ Ab, int ldA,
    const __nv_bfloat16* __restrict__ Bb,
    float* __restrict__ C, int M, int Nc, int K)
{
    __shared__ __align__(16) char smbuf[32768];
    gemm_body(smbuf, Ab, ldA, Bb, C, M, Nc, K, blockIdx.y * 128, blockIdx.x * 128);
}

// recurrent-step GEMM: bx 0..5: [gh0|gi1] = hb0 @ [Whh0;Wih1]^T (Nc=768);
//                      bx 6..8: gh1 = hb1 @ Whh1^T (Nc=384), only if act1.
__global__ void __launch_bounds__(256) gemm2_k(
    const __nv_bfloat16* __restrict__ hb0,
    const __nv_bfloat16* __restrict__ hb1,
    const __nv_bfloat16* __restrict__ Bs0,
    const __nv_bfloat16* __restrict__ Bhh1,
    float* __restrict__ g01, float* __restrict__ gh1, int act1)
{
    __shared__ __align__(16) char smbuf[32768];
    const int bx = blockIdx.x;
    const int bm = blockIdx.y * 128;
    if (bx < 6) {
        gemm_body(smbuf, hb0, 2 * HH, Bs0, g01, NN, 768, HH, bm, bx * 128);
    } else {
        if (!act1) return;
        gemm_body(smbuf, hb1, 2 * HH, Bhh1, gh1, NN, G3, HH, bm, (bx - 6) * 128);
    }
}

// ---------------- dual-layer GRU pointwise cell ----------------
__global__ void cell2_k(const float* __restrict__ gi0, const float* __restrict__ g01,
                        const float* __restrict__ gh1,
                        const float* __restrict__ bih0, const float* __restrict__ bhh0,
                        float* __restrict__ h0, __nv_bfloat16* __restrict__ hb0,
                        const float* __restrict__ bih1, const float* __restrict__ bhh1,
                        float* __restrict__ h1, __nv_bfloat16* __restrict__ hb1,
                        int t0, int act0, int act1) {
    int idx = blockIdx.x * blockDim.x + threadIdx.x;
    if (idx >= NN * HH) return;
    int i = idx >> 7;
    int j = idx & 127;
    if (blockIdx.y == 0) {
        if (!act0) return;
        size_t mg = ((size_t)i * TT + t0) * G3;
        size_t hg = (size_t)i * 768;
        float ir  = gi0[mg + j]          + bih0[j];
        float iz  = gi0[mg + HH + j]     + bih0[HH + j];
        float inn = gi0[mg + 2 * HH + j] + bih0[2 * HH + j];
        float hr  = g01[hg + j]          + bhh0[j];
        float hz  = g01[hg + HH + j]     + bhh0[HH + j];
        float hn  = g01[hg + 2 * HH + j] + bhh0[2 * HH + j];
        float r = 1.f / (1.f + expf(-(ir + hr)));
        float z = 1.f / (1.f + expf(-(iz + hz)));
        float n = tanhf(inn + r * hn);
        float hold = h0[idx];
        float hnew = (1.f - z) * n + z * hold;
        h0[idx] = hnew;
        __nv_bfloat16 hi = __float2bfloat16(hnew);
        __nv_bfloat16 lo = __float2bfloat16(hnew - __bfloat162float(hi));
        hb0[(size_t)i * 256 + j]      = hi;
        hb0[(size_t)i * 256 + HH + j] = lo;
    } else {
        if (!act1) return;
        size_t ig = (size_t)i * 768 + 384;     // gi1 slice of g01
        size_t hg = (size_t)i * G3;
        float ir  = g01[ig + j]          + bih1[j];
        float iz  = g01[ig + HH + j]     + bih1[HH + j];
        float inn = g01[ig + 2 * HH + j] + bih1[2 * HH + j];
        float hr  = gh1[hg + j]          + bhh1[j];
        float hz  = gh1[hg + HH + j]     + bhh1[HH + j];
        float hn  = gh1[hg + 2 * HH + j] + bhh1[2 * HH + j];
        float r = 1.f / (1.f + expf(-(ir + hr)));
        float z = 1.f / (1.f + expf(-(iz + hz)));
        float n = tanhf(inn + r * hn);
        float hold = h1[idx];
        float hnew = (1.f - z) * n + z * hold;
        h1[idx] = hnew;
        __nv_bfloat16 hi = __float2bfloat16(hnew);
        __nv_bfloat16 lo = __float2bfloat16(hnew - __bfloat162float(hi));
        hb1[(size_t)i * 256 + j]      = hi;
        hb1[(size_t)i * 256 + HH + j] = lo;
    }
}

// ---------------- GAT kernels ----------------
__global__ void gat_scores_k(const float* __restrict__ hlin,
                             const float* __restrict__ asrc, const float* __restrict__ adst,
                             float* __restrict__ es, float* __restrict__ ed,
                             unsigned* __restrict__ mu, int n) {
    int g = blockIdx.x * blockDim.x + threadIdx.x;
    int node = g >> 5;
    int lane = g & 31;
    if (node >= n) return;
    float4 h4 = reinterpret_cast<const float4*>(hlin + (size_t)node * HH)[lane];
    float4 a4 = reinterpret_cast<const float4*>(asrc)[lane];
    float4 d4 = reinterpret_cast<const float4*>(adst)[lane];
    float s = h4.x * a4.x + h4.y * a4.y + h4.z * a4.z + h4.w * a4.w;
    float d = h4.x * d4.x + h4.y * d4.y + h4.z * d4.z + h4.w * d4.w;
#pragma unroll
    for (int o = 16; o; o >>= 1) {
        s += __shfl_xor_sync(0xffffffffu, s, o);
        d += __shfl_xor_sync(0xffffffffu, d, o);
    }
    if (lane == 0) {
        es[node] = s;
        ed[node] = d;
        mu[node] = fkey(lrelu(s + d));
    }
}

__global__ void gat_edge_max_k(const int* __restrict__ ei,
                               const float* __restrict__ es, const float* __restrict__ ed,
                               float* __restrict__ eedge, unsigned* __restrict__ mu, int E) {
    int e = blockIdx.x * blockDim.x + threadIdx.x;
    if (e >= E) return;
    int s = ei[e];
    int d = ei[E + e];
    float v = lrelu(es[s] + ed[d]);
    eedge[e] = v;
    atomicMax(&mu[d], fkey(v));
}

__global__ void gat_node_init_k(const float* __restrict__ hlin,
                                const float* __restrict__ es, const float* __restrict__ ed,
                                const unsigned* __restrict__ mu,
                                float* __restrict__ m, float* __restrict__ den,
                                float* __restrict__ acc) {
    int i = blockIdx.x;
    int j = threadIdx.x;
    float mv = funkey(mu[i]);
    float w0 = expf(lrelu(es[i] + ed[i]) - mv);
    if (j == 0) { m[i] = mv; den[i] = w0; }
    acc[(size_t)i * HH + j] = w0 * hlin[(size_t)i * HH + j];
}

__global__ void gat_edge_agg_k(const int* __restrict__ ei, const float* __restrict__ eedge,
                               const float* __restrict__ m, const float* __restrict__ hlin,
                               float* __restrict__ den, float* __restrict__ acc, int E) {
    int g = blockIdx.x * blockDim.x + threadIdx.x;
    int e = g >> 5;
    int lane = g & 31;
    if (e >= E) return;
    int s = ei[e];
    int d = ei[E + e];
    float w = expf(eedge[e] - m[d]);
    if (lane == 0) atomicAdd(&den[d], w);
    float4 hv = reinterpret_cast<const float4*>(hlin + (size_t)s * HH)[lane];
    float* ap = acc + (size_t)d * HH + 4 * lane;
    red_add_v4(ap, w * hv.x, w * hv.y, w * hv.z, w * hv.w);
}

__global__ void gat_finalize_k(float* __restrict__ acc, const float* __restrict__ den,
                               const float* __restrict__ bias) {
    int i = blockIdx.x;
    int j = threadIdx.x;
    acc[(size_t)i * HH + j] = acc[(size_t)i * HH + j] / den[i] + bias[j];
}

// ---------------- sector max pool ----------------
__global__ void pool_max_k(const float* __restrict__ x, const int* __restrict__ sid,
                           unsigned* __restrict__ pu) {
    int idx = blockIdx.x * blockDim.x + threadIdx.x;
    if (idx >= NN * HH) return;
    int i = idx >> 7;
    int j = idx & 127;
    atomicMax(&pu[sid[i] * HH + j], fkey(x[idx]));
}
__global__ void pool_conv_k(const unsigned* __restrict__ pu, float* __restrict__ p,
                            __nv_bfloat16* __restrict__ pb) {
    int idx = blockIdx.x * blockDim.x + threadIdx.x;
    if (idx >= SS * HH) return;
    int r = idx >> 7, j = idx & 127;
    float v = funkey(pu[idx]);
    p[idx] = v;
    __nv_bfloat16 hi = __float2bfloat16(v);
    __nv_bfloat16 lo = __float2bfloat16(v - __bfloat162float(hi));
    pb[(size_t)r * 2 * HH + j]      = hi;
    pb[(size_t)r * 2 * HH + HH + j] = lo;
}

// ---------------- fusion head ----------------
__global__ void fusion_k(const float* __restrict__ seq, const float* __restrict__ intra,
                         const float* __restrict__ inter, const int* __restrict__ sid,
                         const float* __restrict__ fw, const float* __restrict__ fb,
                         float* __restrict__ out) {
    int g = blockIdx.x * blockDim.x + threadIdx.x;
    int i = g >> 5;
    int lane = g & 31;
    if (i >= NN) return;
    int sc = sid[i];
    const float4* s4 = reinterpret_cast<const float4*>(seq + (size_t)i * HH);
    const float4* i4 = reinterpret_cast<const float4*>(intra + (size_t)i * HH);
    const float4* e4 = reinterpret_cast<const float4*>(inter + (size_t)sc * HH);
    const float4* w4 = reinterpret_cast<const float4*>(fw);
    float sum = 0.f;
    float4 a, b;
    a = s4[lane]; b = w4[lane];
    sum += a.x * b.x + a.y * b.y + a.z * b.z + a.w * b.w;
    a = i4[lane]; b = w4[32 + lane];
    sum += a.x * b.x + a.y * b.y + a.z * b.z + a.w * b.w;
    a = e4[lane]; b = w4[64 + lane];
    sum += a.x * b.x + a.y * b.y + a.z * b.z + a.w * b.w;
#pragma unroll
    for (int o = 16; o; o >>= 1) sum += __shfl_xor_sync(0xffffffffu, sum, o);
    if (lane == 0) out[i] = sum + fb[0];
}

// ---------------- host ----------------
static inline void launch_gemm(const __nv_bfloat16* Ab, const __nv_bfloat16* Bb,
                               float* C, int M, int Nc, int K) {
    dim3 grid(Nc / 128, (M + 127) / 128);
    gemm_mma_k<<<grid, 256>>>(Ab, 2 * K, Bb, C, M, Nc, K);
}

extern "C" void kernel_launch(void* const* d_in, const int* in_sizes, int n_in,
                              void* d_out, int out_size) {
    const float* x        = (const float*)d_in[0];
    const int*   ei_intra = (const int*)d_in[1];
    const int*   ei_inter = (const int*)d_in[2];
    const int*   sid      = (const int*)d_in[3];
    const float* w_ih0 = (const float*)d_in[4];
    const float* w_hh0 = (const float*)d_in[5];
    const float* b_ih0 = (const float*)d_in[6];
    const float* b_hh0 = (const float*)d_in[7];
    const float* w_ih1 = (const float*)d_in[8];
    const float* w_hh1 = (const float*)d_in[9];
    const float* b_ih1 = (const float*)d_in[10];
    const float* b_hh1 = (const float*)d_in[11];
    const float* intra_W  = (const float*)d_in[12];
    const float* a_src_i  = (const float*)d_in[13];
    const float* a_dst_i  = (const float*)d_in[14];
    const float* bias_i   = (const float*)d_in[15];
    const float* inter_W  = (const float*)d_in[16];
    const float* a_src_e  = (const float*)d_in[17];
    const float* a_dst_e  = (const float*)d_in[18];
    const float* bias_e   = (const float*)d_in[19];
    const float* fw       = (const float*)d_in[20];
    const float* fb       = (const float*)d_in[21];
    float* out = (float*)d_out;

    float *gi, *g01, *gh1, *h0, *h1, *hlin, *acc;
    float *es, *ed, *m, *den, *eedge, *pool, *shlin, *sacc;
    __nv_bfloat16 *xb, *hb0, *hb1, *wb_ih0, *wb_s0, *wb_hh1, *wb_a, *wb_e, *poolb;
    unsigned *mu, *pu;
    cudaGetSymbolAddress((void**)&gi, g_gi);
    cudaGetSymbolAddress((void**)&xb, g_xb);
    cudaGetSymbolAddress((void**)&g01, g_g01);
    cudaGetSymbolAddress((void**)&gh1, g_gh1);
    cudaGetSymbolAddress((void**)&h0, g_h0);
    cudaGetSymbolAddress((void**)&h1, g_h1);
    cudaGetSymbolAddress((void**)&hb0, g_hb0);
    cudaGetSymbolAddress((void**)&hb1, g_hb1);
    cudaGetSymbolAddress((void**)&hlin, g_hlin);
    cudaGetSymbolAddress((void**)&acc, g_acc);
    cudaGetSymbolAddress((void**)&wb_ih0, g_wb_ih0);
    cudaGetSymbolAddress((void**)&wb_s0, g_wb_s0);
    cudaGetSymbolAddress((void**)&wb_hh1, g_wb_hh1);
    cudaGetSymbolAddress((void**)&wb_a, g_wb_intra);
    cudaGetSymbolAddress((void**)&wb_e, g_wb_inter);
    cudaGetSymbolAddress((void**)&es, g_es);
    cudaGetSymbolAddress((void**)&ed, g_ed);
    cudaGetSymbolAddress((void**)&m, g_m);
    cudaGetSymbolAddress((void**)&den, g_den);
    cudaGetSymbolAddress((void**)&mu, g_mu);
    cudaGetSymbolAddress((void**)&eedge, g_eedge);
    cudaGetSymbolAddress((void**)&pu, g_pu);
    cudaGetSymbolAddress((void**)&pool, g_pool);
    cudaGetSymbolAddress((void**)&poolb, g_poolb);
    cudaGetSymbolAddress((void**)&shlin, g_shlin);
    cudaGetSymbolAddress((void**)&sacc, g_sacc);

    const int cellGrid = (NN * HH + 255) / 256;

    // ---- prep (ordered so launch #5 == gemm_mma_k for ncu -s 5 -c 1) ----
    convw_k<<<(G3 * INP + 255) / 256, 256>>>(w_ih0, wb_ih0, G3, INP);                 // 0
    convw_k<<<(NN * TT * INP + 255) / 256, 256>>>(x, xb, NN * TT, INP);               // 1
    convw_k<<<(G3 * HH + 255) / 256, 256>>>(w_hh0, wb_s0, G3, HH);                    // 2
    convw_k<<<(G3 * HH + 255) / 256, 256>>>(w_ih1, wb_s0 + (size_t)G3 * 2 * HH, G3, HH); // 3
    convw_k<<<(G3 * HH + 255) / 256, 256>>>(w_hh1, wb_hh1, G3, HH);                   // 4
    launch_gemm(xb, wb_ih0, gi, NN * TT, G3, INP);                                    // 5 <- profiled
    zerof_k<<<(NN * HH + 255) / 256, 256>>>(h0, NN * HH);
    zerof_k<<<(NN * HH + 255) / 256, 256>>>(h1, NN * HH);
    zerou_k<<<(NN * HH + 255) / 256, 256>>>((unsigned*)hb0, NN * HH);
    zerou_k<<<(NN * HH + 255) / 256, 256>>>((unsigned*)hb1, NN * HH);

    // ---- pipelined GRU: iteration it = layer0 step it & layer1 step it-1 ----
    const dim3 g2grid(9, (NN + 127) / 128);
    const dim3 cellG(cellGrid, 2);
    for (int it = 0; it <= TT; it++) {
        const int act0 = (it < TT) ? 1 : 0;
        const int act1 = (it >= 1) ? 1 : 0;
        gemm2_k<<<g2grid, 256>>>(hb0, hb1, wb_s0, wb_hh1, g01, gh1, act1);
        cell2_k<<<cellG, 256>>>(gi, g01, gh1, b_ih0, b_hh0, h0, hb0,
                                b_ih1, b_hh1, h1, hb1, it, act0, act1);
    }
    // h1 == seq_emb (fp32), hb1 == its bf16 split

    // ---- intra GAT ----
    convw_k<<<(HH * HH + 255) / 256, 256>>>(intra_W, wb_a, HH, HH);
    launch_gemm(hb1, wb_a, hlin, NN, HH, HH);
    gat_scores_k<<<(NN * 32 + 255) / 256, 256>>>(hlin, a_src_i, a_dst_i, es, ed, mu, NN);
    gat_edge_max_k<<<(EINTRA + 255) / 256, 256>>>(ei_intra, es, ed, eedge, mu, EINTRA);
    gat_node_init_k<<<NN, HH>>>(hlin, es, ed, mu, m, den, acc);
    gat_edge_agg_k<<<(EINTRA * 32 + 255) / 256, 256>>>(ei_intra, eedge, m, hlin, den, acc, EINTRA);
    gat_finalize_k<<<NN, HH>>>(acc, den, bias_i);
    // acc == intra_emb

    // ---- sector max pool ----
    zerou_k<<<(SS * HH + 255) / 256, 256>>>(pu, SS * HH);
    pool_max_k<<<(NN * HH + 255) / 256, 256>>>(acc, sid, pu);
    pool_conv_k<<<(SS * HH + 255) / 256, 256>>>(pu, pool, poolb);

    // ---- inter GAT (S=64) ----
    convw_k<<<(HH * HH + 255) / 256, 256>>>(inter_W, wb_e, HH, HH);
    launch_gemm(poolb, wb_e, shlin, SS, HH, HH);
    gat_scores_k<<<(SS * 32 + 255) / 256, 256>>>(shlin, a_src_e, a_dst_e, es, ed, mu, SS);
    gat_edge_max_k<<<(EINTER + 255) / 256, 256>>>(ei_inter, es, ed, eedge, mu, EINTER);
    gat_node_init_k<<<SS, HH>>>(shlin, es, ed, mu, m, den, sacc);
    gat_edge_agg_k<<<(EINTER * 32 + 255) / 256, 256>>>(ei_inter, eedge, m, shlin, den, sacc, EINTER);
    gat_finalize_k<<<SS, HH>>>(sacc, den, bias_e);
    // sacc == inter_sec

    // ---- fusion ----
    fusion_k<<<(NN * 32 + 255) / 256, 256>>>(h1, acc, sacc, sid, fw, fb, out);
}